// round 8
// baseline (speedup 1.0000x reference)
#include <cuda_runtime.h>

#define TT 512
#define BB 256
#define II 64
#define HH 512
#define G3 1536
#define RT (TT*BB)
#define KC 64
#define NCH (HH/KC)          // 8
#define AS 68                // A chunk row stride (floats)
#define ASZ (32*AS)          // 2176 floats per A buffer
#define NBUF 3
#define BST 516              // resident W row stride (floats)
#define SMEM_STEP ((96*BST + NBUF*ASZ)*4)   // 224256 bytes

typedef unsigned long long u64;

__device__ float g_giT[(size_t)TT * G3 * BB];   // [t][gate*H+unit][batch]
__device__ float g_Z  [(size_t)RT * HH];        // [t][b][h]
__device__ float g_h0 [BB * HH];                // zeros
__device__ unsigned g_flag[TT * 8 * 16];        // [t][bx][by], one-shot per launch
struct __align__(128) Bar { unsigned cnt; unsigned gen; unsigned pad[30]; };
__device__ Bar g_bar0;

__device__ __forceinline__ u64 ffma2(u64 a, u64 b, u64 c){
    u64 d;
    asm("fma.rn.f32x2 %0, %1, %2, %3;" : "=l"(d) : "l"(a), "l"(b), "l"(c));
    return d;
}
__device__ __forceinline__ float pairsum(u64 v){
    float lo, hi;
    asm("mov.b64 {%0, %1}, %2;" : "=f"(lo), "=f"(hi) : "l"(v));
    return lo + hi;
}
__device__ __forceinline__ float sigf(float x){
    return __fdividef(1.0f, 1.0f + __expf(-x));
}
__device__ __forceinline__ void cpa16(float* dst, const float* src){
    unsigned d = (unsigned)__cvta_generic_to_shared(dst);
    asm volatile("cp.async.ca.shared.global [%0], [%1], 16;" :: "r"(d), "l"(src));
}
__device__ __forceinline__ void cpa_commit(){ asm volatile("cp.async.commit_group;"); }
__device__ __forceinline__ void waitpair(const unsigned* p){
    u64 v;
    do {
        asm volatile("ld.acquire.gpu.u64 %0, [%1];" : "=l"(v) : "l"(p) : "memory");
    } while (v != 0x0000000100000001ULL);
}

// ---------------- Phase 1: giT[t][c][b] = X[t,b,:] . Wih[c,:] + bih[c] ----------------
#define GIS 66
__global__ __launch_bounds__(256) void gi_kernel(const float* __restrict__ X,
                                                 const float* __restrict__ Wih,
                                                 const float* __restrict__ bih)
{
    __shared__ __align__(16) float Xs[64 * GIS];
    __shared__ __align__(16) float Ws[64 * GIS];
    const int r0 = blockIdx.x * 64;
    const int c0 = blockIdx.y * 64;
    const int t  = threadIdx.x;

    #pragma unroll
    for (int j = 0; j < 4; j++){
        int q   = t + 256 * j;
        int row = q >> 4;
        int kq  = q & 15;
        const u64* gx = reinterpret_cast<const u64*>(&X[(size_t)(r0+row)*II + kq*4]);
        u64* px = reinterpret_cast<u64*>(&Xs[row*GIS + kq*4]);
        px[0] = gx[0]; px[1] = gx[1];
        const u64* gw = reinterpret_cast<const u64*>(&Wih[(size_t)(c0+row)*II + kq*4]);
        u64* pw = reinterpret_cast<u64*>(&Ws[row*GIS + kq*4]);
        pw[0] = gw[0]; pw[1] = gw[1];
    }
    __syncthreads();

    const int tm = t & 15;
    const int tn = t >> 4;
    u64 acc[4][4];
    #pragma unroll
    for (int i = 0; i < 4; i++)
        #pragma unroll
        for (int j = 0; j < 4; j++) acc[i][j] = 0ull;

    #pragma unroll 8
    for (int k = 0; k < 64; k += 2){
        u64 a[4], b[4];
        #pragma unroll
        for (int i = 0; i < 4; i++)
            a[i] = *reinterpret_cast<const u64*>(&Xs[(tm+16*i)*GIS + k]);
        #pragma unroll
        for (int j = 0; j < 4; j++)
            b[j] = *reinterpret_cast<const u64*>(&Ws[(tn+16*j)*GIS + k]);
        #pragma unroll
        for (int i = 0; i < 4; i++)
            #pragma unroll
            for (int j = 0; j < 4; j++)
                acc[i][j] = ffma2(a[i], b[j], acc[i][j]);
    }

    #pragma unroll
    for (int i = 0; i < 4; i++){
        #pragma unroll
        for (int j = 0; j < 4; j++){
            int c = c0 + tn + 16*j;
            int r = r0 + tm + 16*i;
            g_giT[((size_t)(r >> 8) * G3 + c) * BB + (r & 255)] = pairsum(acc[i][j]) + bih[c];
        }
    }
}

// ---------------- Phase 2: persistent GRU, stationary weights, flag sync ----------------
__global__ __launch_bounds__(256, 1) void step_persist(const float* __restrict__ Whh,
                                                       const float* __restrict__ bhh)
{
    extern __shared__ __align__(16) float sm[];
    float* Bw  = sm;                 // [96][BST] resident weights
    float* Asb = sm + 96*BST;        // [NBUF][ASZ] h chunks

    const int bx  = blockIdx.x;          // 8 batch groups
    const int by  = blockIdx.y;          // 16 hidden groups
    const int b0  = bx * 32;
    const int h0  = by * 32;
    const int tid = threadIdx.x;
    const int mq  = tid & 7;             // batches b0 + mq + 8i
    const int u   = tid >> 3;            // unit 0..31
    const int jg  = h0 + u;

    const float bhr = bhh[jg], bhz = bhh[HH + jg], bhn = bhh[2*HH + jg];

    // ---- load resident weights (once): 96 rows x 512 floats ----
    #pragma unroll 4
    for (int jj = 0; jj < 48; jj++){
        int idx = tid + 256*jj;          // 0..12287
        int row = idx >> 7;              // 0..95
        int c4  = idx & 127;             // float4 index in row
        int gr  = (row >> 5) * HH + h0 + (row & 31);
        cpa16(&Bw[row*BST + c4*4], &Whh[(size_t)gr*HH + c4*4]);
    }
    cpa_commit();

    // ---- clear this CTA's flags, then one-time global barrier ----
    for (int i = tid; i < TT; i += 256)
        g_flag[(i*8 + bx)*16 + by] = 0;
    __threadfence();
    __syncthreads();
    unsigned gen;
    asm volatile("ld.acquire.gpu.u32 %0, [%1];" : "=r"(gen) : "l"(&g_bar0.gen) : "memory");
    if (tid == 0){
        unsigned arr = atomicAdd(&g_bar0.cnt, 1);
        if (arr == 127){
            atomicExch(&g_bar0.cnt, 0);
            __threadfence();
            atomicAdd(&g_bar0.gen, 1);
        } else {
            unsigned g;
            do {
                __nanosleep(32);
                asm volatile("ld.acquire.gpu.u32 %0, [%1];" : "=r"(g) : "l"(&g_bar0.gen) : "memory");
            } while (g == gen);
        }
    }
    __syncthreads();
    asm volatile("cp.async.wait_group 0;");
    __syncthreads();                      // weights resident

    float hp[4];
    #pragma unroll
    for (int i = 0; i < 4; i++) hp[i] = 0.0f;

    for (int t = 0; t < TT; t++){
        const float* hprev = (t == 0) ? g_h0 : (g_Z + (size_t)(t-1)*BB*HH);
        float*       hout  = g_Z + (size_t)t * BB * HH;
        const float* git   = g_giT + (size_t)t * G3 * BB;

        // epilogue operand prefetch
        float gv[3][4];
        #pragma unroll
        for (int i = 0; i < 4; i++){
            int b = b0 + mq + 8*i;
            gv[0][i] = git[(size_t)(        jg)*BB + b];
            gv[1][i] = git[(size_t)(HH   + jg)*BB + b];
            gv[2][i] = git[(size_t)(2*HH + jg)*BB + b];
        }

        // chunk 0: flag-gated issue
        if (t > 0) waitpair(&g_flag[((t-1)*8 + bx)*16 + 0]);
        #pragma unroll
        for (int jj = 0; jj < 2; jj++){
            int idx = tid + 256*jj, row = idx >> 4, kq = idx & 15;
            cpa16(&Asb[row*AS + kq*4], &hprev[(size_t)(b0+row)*HH + kq*4]);
        }
        cpa_commit();

        u64 accr[4], accz[4], accn[4];
        #pragma unroll
        for (int i = 0; i < 4; i++){ accr[i]=0ull; accz[i]=0ull; accn[i]=0ull; }

        #pragma unroll 1
        for (int c = 0; c < NCH; c++){
            if (c < NCH-1){
                int nb = (c+1) % NBUF, k0 = (c+1)*KC;
                if (t > 0) waitpair(&g_flag[((t-1)*8 + bx)*16 + 2*(c+1)]);
                #pragma unroll
                for (int jj = 0; jj < 2; jj++){
                    int idx = tid + 256*jj, row = idx >> 4, kq = idx & 15;
                    cpa16(&Asb[nb*ASZ + row*AS + kq*4], &hprev[(size_t)(b0+row)*HH + k0 + kq*4]);
                }
                cpa_commit();
                asm volatile("cp.async.wait_group 1;");
            } else {
                asm volatile("cp.async.wait_group 0;");
            }
            __syncthreads();

            const float* Ab = Asb + (c % NBUF)*ASZ;
            const ulonglong2* pbr = reinterpret_cast<const ulonglong2*>(&Bw[(     u)*BST + c*KC]);
            const ulonglong2* pbz = reinterpret_cast<const ulonglong2*>(&Bw[(32 + u)*BST + c*KC]);
            const ulonglong2* pbn = reinterpret_cast<const ulonglong2*>(&Bw[(64 + u)*BST + c*KC]);
            #pragma unroll
            for (int k4 = 0; k4 < KC/4; k4++){
                ulonglong2 vr = pbr[k4];
                ulonglong2 vz = pbz[k4];
                ulonglong2 vn = pbn[k4];
                #pragma unroll
                for (int i = 0; i < 4; i++){
                    ulonglong2 va = *reinterpret_cast<const ulonglong2*>(&Ab[(mq+8*i)*AS + k4*4]);
                    accr[i] = ffma2(va.x, vr.x, accr[i]);
                    accr[i] = ffma2(va.y, vr.y, accr[i]);
                    accz[i] = ffma2(va.x, vz.x, accz[i]);
                    accz[i] = ffma2(va.y, vz.y, accz[i]);
                    accn[i] = ffma2(va.x, vn.x, accn[i]);
                    accn[i] = ffma2(va.y, vn.y, accn[i]);
                }
            }
        }

        // fused gate epilogue (h carried in registers)
        #pragma unroll
        for (int i = 0; i < 4; i++){
            int b = b0 + mq + 8*i;
            float pr = pairsum(accr[i]) + bhr;
            float pz = pairsum(accz[i]) + bhz;
            float pn = pairsum(accn[i]) + bhn;
            float r  = sigf(gv[0][i] + pr);
            float z  = sigf(gv[1][i] + pz);
            float nn = tanhf(gv[2][i] + r * pn);
            float hn = (1.0f - z) * nn + z * hp[i];
            hp[i] = hn;
            hout[(size_t)b*HH + jg] = hn;
        }

        __syncthreads();
        if (tid == 0){
            __threadfence();
            asm volatile("st.release.gpu.u32 [%0], %1;"
                         :: "l"(&g_flag[((size_t)t*8 + bx)*16 + by]), "r"(1u) : "memory");
        }
    }
}

// ---------------- Phase 3: V = bias + Z . vw ----------------
__global__ __launch_bounds__(256) void value_kernel(const float* __restrict__ vw,
                                                    const float* __restrict__ bias,
                                                    float* __restrict__ out)
{
    int warp = (blockIdx.x * 256 + threadIdx.x) >> 5;
    int lane = threadIdx.x & 31;
    const float* z = g_Z + (size_t)warp * HH;
    float s = 0.0f;
    #pragma unroll
    for (int i = 0; i < 4; i++){
        int idx = i*128 + lane*4;
        float4 zv = *reinterpret_cast<const float4*>(&z[idx]);
        float4 wv = *reinterpret_cast<const float4*>(&vw[idx]);
        s += zv.x*wv.x + zv.y*wv.y + zv.z*wv.z + zv.w*wv.w;
    }
    #pragma unroll
    for (int o = 16; o > 0; o >>= 1)
        s += __shfl_xor_sync(0xFFFFFFFFu, s, o);
    if (lane == 0) out[warp] = s + bias[0];
}

extern "C" void kernel_launch(void* const* d_in, const int* in_sizes, int n_in,
                              void* d_out, int out_size)
{
    const float* X    = (const float*)d_in[0];
    const float* Wih  = (const float*)d_in[1];
    const float* Whh  = (const float*)d_in[2];
    const float* bih  = (const float*)d_in[3];
    const float* bhh  = (const float*)d_in[4];
    const float* vw   = (const float*)d_in[5];
    const float* bias = (const float*)d_in[6];
    float* out = (float*)d_out;

    static int smem_set = 0;
    if (!smem_set){
        cudaFuncSetAttribute(step_persist, cudaFuncAttributeMaxDynamicSharedMemorySize, SMEM_STEP);
        smem_set = 1;
    }

    dim3 ggi(RT/64, G3/64);
    gi_kernel<<<ggi, 256>>>(X, Wih, bih);

    dim3 gst(BB/32, HH/32);   // 8 x 16 = 128 CTAs, all resident
    step_persist<<<gst, 256, SMEM_STEP>>>(Whh, bhh);

    value_kernel<<<RT/8, 256>>>(vw, bias, out);
}

// round 10
// speedup vs baseline: 2.4606x; 2.4606x over previous
#include <cuda_runtime.h>
#include <cuda_bf16.h>
#include <cstdint>

#define TT 512
#define BB 256
#define II 64
#define HH 512
#define G3 1536
#define RT (TT*BB)

typedef unsigned long long u64;

// ---------------- scratch ----------------
__device__ float g_gi2[(size_t)TT * 32 * 256 * 48];   // [t][hg][b][jl+16*gate]
__device__ __nv_bfloat16 g_Zh[(size_t)RT * HH];       // h hi [t][b][k]
__device__ __nv_bfloat16 g_Zl[(size_t)RT * HH];       // h lo
__device__ __nv_bfloat16 g_zh0[BB * HH];              // zeros
__device__ unsigned g_cnt[TT * 4];                    // [t][quarter]
struct __align__(128) Bar { unsigned cnt; unsigned gen; unsigned pad[30]; };
__device__ Bar g_bar0;

// ---------------- smem layout ----------------
#define SM_BIAS 0
#define A_OFF   1024
#define ABUF    32768                 // per buffer: hi 16K + lo 16K
#define BH_OFF  (1024 + 2*ABUF)      // 66560
#define BL_OFF  (BH_OFF + 49152)     // 115712
#define SMEM_TC (BL_OFF + 49152)     // 164864

static __device__ __forceinline__ uint32_t s2u(const void* p){
    return (uint32_t)__cvta_generic_to_shared(p);
}
static __device__ __forceinline__ float sigf(float x){
    return __fdividef(1.0f, 1.0f + __expf(-x));
}
static __device__ __forceinline__ void cpa16(uint32_t dst, const void* src){
    asm volatile("cp.async.ca.shared.global [%0], [%1], 16;" :: "r"(dst), "l"(src));
}
static __device__ __forceinline__ void ldsm4(uint32_t a, uint32_t (&r)[4]){
    asm volatile("ldmatrix.sync.aligned.m8n8.x4.shared.b16 {%0,%1,%2,%3}, [%4];"
        : "=r"(r[0]), "=r"(r[1]), "=r"(r[2]), "=r"(r[3]) : "r"(a));
}
static __device__ __forceinline__ void mma16816(float (&d)[4], const uint32_t (&a)[4],
                                                const uint32_t* b){
    asm volatile("mma.sync.aligned.m16n8k16.row.col.f32.bf16.bf16.f32 "
        "{%0,%1,%2,%3}, {%4,%5,%6,%7}, {%8,%9}, {%0,%1,%2,%3};"
        : "+f"(d[0]), "+f"(d[1]), "+f"(d[2]), "+f"(d[3])
        : "r"(a[0]), "r"(a[1]), "r"(a[2]), "r"(a[3]), "r"(b[0]), "r"(b[1]));
}

// ---------------- Phase 1: gi in consumer layout ----------------
#define GIS 66
__global__ __launch_bounds__(256) void gi_kernel(const float* __restrict__ X,
                                                 const float* __restrict__ Wih,
                                                 const float* __restrict__ bih)
{
    __shared__ __align__(16) float Xs[64 * GIS];
    __shared__ __align__(16) float Ws[64 * GIS];
    const int r0 = blockIdx.x * 64;
    const int c0 = blockIdx.y * 64;
    const int t  = threadIdx.x;

    #pragma unroll
    for (int j = 0; j < 4; j++){
        int q   = t + 256 * j;
        int row = q >> 4;
        int kq  = q & 15;
        const u64* gx = reinterpret_cast<const u64*>(&X[(size_t)(r0+row)*II + kq*4]);
        u64* px = reinterpret_cast<u64*>(&Xs[row*GIS + kq*4]);
        px[0] = gx[0]; px[1] = gx[1];
        const u64* gw = reinterpret_cast<const u64*>(&Wih[(size_t)(c0+row)*II + kq*4]);
        u64* pw = reinterpret_cast<u64*>(&Ws[row*GIS + kq*4]);
        pw[0] = gw[0]; pw[1] = gw[1];
    }
    __syncthreads();

    const int tm = t & 15;
    const int tn = t >> 4;
    float acc[4][4];
    #pragma unroll
    for (int i = 0; i < 4; i++)
        #pragma unroll
        for (int j = 0; j < 4; j++) acc[i][j] = 0.0f;

    #pragma unroll 8
    for (int k = 0; k < 64; k++){
        float a[4], b[4];
        #pragma unroll
        for (int i = 0; i < 4; i++) a[i] = Xs[(tm+16*i)*GIS + k];
        #pragma unroll
        for (int j = 0; j < 4; j++) b[j] = Ws[(tn+16*j)*GIS + k];
        #pragma unroll
        for (int i = 0; i < 4; i++)
            #pragma unroll
            for (int j = 0; j < 4; j++)
                acc[i][j] = fmaf(a[i], b[j], acc[i][j]);
    }

    #pragma unroll
    for (int i = 0; i < 4; i++){
        #pragma unroll
        for (int j = 0; j < 4; j++){
            int c = c0 + tn + 16*j;
            int r = r0 + tm + 16*i;
            int tt = r >> 8, bb = r & 255;
            int gate = c >> 9, ju = c & 511;
            int hg = ju >> 4, jl = ju & 15;
            g_gi2[((((size_t)tt*32 + hg)*256 + bb)*48) + jl + (gate<<4)] = acc[i][j] + bih[c];
        }
    }
}

// ---------------- Phase 2: persistent HMMA GRU ----------------
__global__ __launch_bounds__(128, 1) void step_tc(const float* __restrict__ Whh,
                                                  const float* __restrict__ bhh)
{
    extern __shared__ __align__(1024) char smem[];
    const uint32_t sb = s2u(smem);
    const int tid  = threadIdx.x;
    const int wid  = tid >> 5, lane = tid & 31;
    const int bq   = blockIdx.x;          // 0..3 batch quarter
    const int hg   = blockIdx.y;          // 0..31 hidden group (16 units)
    const int b0   = bq * 64;
    const int h0   = hg * 16;
    const int m0   = wid * 16;
    const int r0   = lane >> 2;
    const int cp   = (lane & 3) * 2;

    float* sBias = (float*)(smem + SM_BIAS);
    if (tid < 48) sBias[tid] = bhh[(tid >> 4)*HH + h0 + (tid & 15)];

    // resident W bf16 split, [n][k] rows with 16B-group XOR swizzle
    for (int it = 0; it < 96; it++){
        int idx = tid + 128*it;           // 0..12287 float2 units
        int n   = idx >> 8;               // 0..47
        int k2  = idx & 255;
        int grow = (n >> 4)*HH + h0 + (n & 15);
        float2 w = *(const float2*)&Whh[(size_t)grow*HH + k2*2];
        __nv_bfloat16 wh0 = __float2bfloat16(w.x);
        __nv_bfloat16 wh1 = __float2bfloat16(w.y);
        __nv_bfloat16 wl0 = __float2bfloat16(w.x - __bfloat162float(wh0));
        __nv_bfloat16 wl1 = __float2bfloat16(w.y - __bfloat162float(wh1));
        int k = k2*2, kg = k >> 3;
        uint32_t off = (uint32_t)(n*1024 + ((kg ^ (n & 7)) << 4) + (k & 7)*2);
        __nv_bfloat162 hv(wh0, wh1), lv(wl0, wl1);
        *(uint32_t*)(smem + BH_OFF + off) = *(uint32_t*)&hv;
        *(uint32_t*)(smem + BL_OFF + off) = *(uint32_t*)&lv;
    }

    // clear counters + one-time global barrier (128 CTAs)
    for (int i = tid; i < TT*4; i += 128) g_cnt[i] = 0;
    __threadfence();
    __syncthreads();
    if (tid == 0){
        unsigned gen;
        asm volatile("ld.acquire.gpu.u32 %0, [%1];" : "=r"(gen) : "l"(&g_bar0.gen) : "memory");
        unsigned arr = atomicAdd(&g_bar0.cnt, 1);
        if (arr == 127){
            atomicExch(&g_bar0.cnt, 0);
            __threadfence();
            atomicAdd(&g_bar0.gen, 1);
        } else {
            unsigned g;
            do { __nanosleep(32);
                 asm volatile("ld.acquire.gpu.u32 %0, [%1];" : "=r"(g) : "l"(&g_bar0.gen) : "memory");
            } while (g == gen);
        }
    }
    __syncthreads();

    float hp[2][2][2];
    #pragma unroll
    for (int a = 0; a < 2; a++)
        #pragma unroll
        for (int b = 0; b < 2; b++)
            #pragma unroll
            for (int c = 0; c < 2; c++) hp[a][b][c] = 0.0f;

    for (int t = 0; t < TT; t++){
        // gi prefetch (independent of h)
        float2 gg[2][3][2];
        #pragma unroll
        for (int rs = 0; rs < 2; rs++){
            int b = b0 + m0 + r0 + 8*rs;
            const float* gp = g_gi2 + ((((size_t)t*32 + hg)*256 + b)*48);
            #pragma unroll
            for (int gate = 0; gate < 3; gate++)
                #pragma unroll
                for (int g = 0; g < 2; g++)
                    gg[rs][gate][g] = __ldg((const float2*)(gp + gate*16 + 8*g + cp));
        }

        if (t > 0){
            if (tid == 0){
                const unsigned* cptr = &g_cnt[(t-1)*4 + bq];
                unsigned v;
                do { asm volatile("ld.acquire.gpu.u32 %0, [%1];" : "=r"(v) : "l"(cptr) : "memory");
                     if (v != 32u) __nanosleep(32);
                } while (v != 32u);
            }
            __syncthreads();
        }
        const __nv_bfloat16* Ah = (t == 0) ? g_zh0 : (g_Zh + (size_t)(t-1)*BB*HH);
        const __nv_bfloat16* Al = (t == 0) ? g_zh0 : (g_Zl + (size_t)(t-1)*BB*HH);

        auto loadA = [&](int j){
            uint32_t ab = sb + A_OFF + (uint32_t)(j & 1)*ABUF;
            #pragma unroll
            for (int q = 0; q < 8; q++){
                int idx = tid + 128*q;           // 0..1023
                int row = idx >> 4, kg = idx & 15;
                uint32_t dst = ab + (uint32_t)(row*256 + ((kg ^ (row & 7)) << 4));
                size_t src = (size_t)(b0+row)*HH + j*128 + kg*8;
                cpa16(dst,           Ah + src);
                cpa16(dst + 16384u,  Al + src);
            }
            asm volatile("cp.async.commit_group;");
        };
        loadA(0); loadA(1);

        float acc[6][4];
        #pragma unroll
        for (int p = 0; p < 6; p++)
            #pragma unroll
            for (int e = 0; e < 4; e++) acc[p][e] = 0.0f;

        #pragma unroll 1
        for (int c = 0; c < 4; c++){
            if (c < 3) asm volatile("cp.async.wait_group 1;");
            else       asm volatile("cp.async.wait_group 0;");
            __syncthreads();

            uint32_t abuf = sb + A_OFF + (uint32_t)(c & 1)*ABUF;
            int rowA = m0 + (lane & 15);
            uint32_t aRowBase = abuf + (uint32_t)(rowA*256);
            #pragma unroll
            for (int s = 0; s < 8; s++){
                uint32_t ah[4], al[4];
                int kgA = s*2 + (lane >> 4);
                uint32_t aoff = aRowBase + (uint32_t)((kgA ^ (lane & 7)) << 4);
                ldsm4(aoff, ah);
                ldsm4(aoff + 16384u, al);
                int kgB = c*16 + s*2 + ((lane >> 3) & 1);
                #pragma unroll
                for (int p = 0; p < 3; p++){
                    int rowB = p*16 + (lane & 7) + ((lane >> 4) << 3);
                    uint32_t boff = (uint32_t)(rowB*1024 + ((kgB ^ (lane & 7)) << 4));
                    uint32_t bh[4], bl[4];
                    ldsm4(sb + BH_OFF + boff, bh);
                    ldsm4(sb + BL_OFF + boff, bl);
                    mma16816(acc[2*p],   ah, bh + 0);
                    mma16816(acc[2*p],   al, bh + 0);
                    mma16816(acc[2*p],   ah, bl + 0);
                    mma16816(acc[2*p+1], ah, bh + 2);
                    mma16816(acc[2*p+1], al, bh + 2);
                    mma16816(acc[2*p+1], ah, bl + 2);
                }
            }
            __syncthreads();
            if (c < 2) loadA(c + 2);
        }

        // fused gate epilogue (thread-local)
        #pragma unroll
        for (int rs = 0; rs < 2; rs++){
            int b = b0 + m0 + r0 + 8*rs;
            uint32_t hw[2], lw[2];
            #pragma unroll
            for (int g = 0; g < 2; g++){
                float hn2[2];
                #pragma unroll
                for (int e = 0; e < 2; e++){
                    int jl = 8*g + cp + e;
                    float pr = acc[0+g][2*rs+e] + sBias[jl];
                    float pz = acc[2+g][2*rs+e] + sBias[16+jl];
                    float pn = acc[4+g][2*rs+e] + sBias[32+jl];
                    const float* gr = (const float*)&gg[rs][0][g];
                    const float* gz = (const float*)&gg[rs][1][g];
                    const float* gn = (const float*)&gg[rs][2][g];
                    float r  = sigf(gr[e] + pr);
                    float z  = sigf(gz[e] + pz);
                    float nn = tanhf(gn[e] + r * pn);
                    float hn = (1.0f - z) * nn + z * hp[rs][g][e];
                    hp[rs][g][e] = hn;
                    hn2[e] = hn;
                }
                __nv_bfloat16 a0 = __float2bfloat16(hn2[0]);
                __nv_bfloat16 a1 = __float2bfloat16(hn2[1]);
                __nv_bfloat16 c0 = __float2bfloat16(hn2[0] - __bfloat162float(a0));
                __nv_bfloat16 c1 = __float2bfloat16(hn2[1] - __bfloat162float(a1));
                __nv_bfloat162 hv(a0, a1), lv(c0, c1);
                hw[g] = *(uint32_t*)&hv;
                lw[g] = *(uint32_t*)&lv;
            }
            size_t o = ((size_t)t*BB + b)*HH + h0 + cp;
            *(uint32_t*)(g_Zh + o)     = hw[0];
            *(uint32_t*)(g_Zh + o + 8) = hw[1];
            *(uint32_t*)(g_Zl + o)     = lw[0];
            *(uint32_t*)(g_Zl + o + 8) = lw[1];
        }

        __threadfence();
        __syncthreads();
        if (tid == 0){
            asm volatile("red.release.gpu.global.add.u32 [%0], %1;"
                         :: "l"(&g_cnt[t*4 + bq]), "r"(1u) : "memory");
        }
    }
}

// ---------------- Phase 3: V = bias + (Zh+Zl) . vw ----------------
__global__ __launch_bounds__(256) void value_kernel(const float* __restrict__ vw,
                                                    const float* __restrict__ bias,
                                                    float* __restrict__ out)
{
    int warp = (blockIdx.x * 256 + threadIdx.x) >> 5;
    int lane = threadIdx.x & 31;
    const __nv_bfloat16* zh = g_Zh + (size_t)warp * HH;
    const __nv_bfloat16* zl = g_Zl + (size_t)warp * HH;
    float s = 0.0f;
    #pragma unroll
    for (int i = 0; i < 4; i++){
        int idx = i*128 + lane*4;
        uint2 ah = *(const uint2*)(zh + idx);
        uint2 al = *(const uint2*)(zl + idx);
        float4 wv = *(const float4*)(&vw[idx]);
        __nv_bfloat162 h0 = *(__nv_bfloat162*)&ah.x;
        __nv_bfloat162 h1 = *(__nv_bfloat162*)&ah.y;
        __nv_bfloat162 l0 = *(__nv_bfloat162*)&al.x;
        __nv_bfloat162 l1 = *(__nv_bfloat162*)&al.y;
        s += (__bfloat162float(h0.x) + __bfloat162float(l0.x)) * wv.x;
        s += (__bfloat162float(h0.y) + __bfloat162float(l0.y)) * wv.y;
        s += (__bfloat162float(h1.x) + __bfloat162float(l1.x)) * wv.z;
        s += (__bfloat162float(h1.y) + __bfloat162float(l1.y)) * wv.w;
    }
    #pragma unroll
    for (int o = 16; o > 0; o >>= 1)
        s += __shfl_xor_sync(0xFFFFFFFFu, s, o);
    if (lane == 0) out[warp] = s + bias[0];
}

extern "C" void kernel_launch(void* const* d_in, const int* in_sizes, int n_in,
                              void* d_out, int out_size)
{
    const float* X    = (const float*)d_in[0];
    const float* Wih  = (const float*)d_in[1];
    const float* Whh  = (const float*)d_in[2];
    const float* bih  = (const float*)d_in[3];
    const float* bhh  = (const float*)d_in[4];
    const float* vw   = (const float*)d_in[5];
    const float* bias = (const float*)d_in[6];
    float* out = (float*)d_out;

    static int smem_set = 0;
    if (!smem_set){
        cudaFuncSetAttribute(step_tc, cudaFuncAttributeMaxDynamicSharedMemorySize, SMEM_TC);
        smem_set = 1;
    }

    dim3 ggi(RT/64, G3/64);
    gi_kernel<<<ggi, 256>>>(X, Wih, bih);

    step_tc<<<dim3(4, 32), 128, SMEM_TC>>>(Whh, bhh);

    value_kernel<<<RT/8, 256>>>(vw, bias, out);
}

// round 11
// speedup vs baseline: 2.5358x; 1.0306x over previous
#include <cuda_runtime.h>
#include <cuda_bf16.h>
#include <cstdint>

#define TT 512
#define BB 256
#define II 64
#define HH 512
#define G3 1536
#define RT (TT*BB)

typedef unsigned long long u64;

// ---------------- scratch ----------------
__device__ float g_gi2[(size_t)TT * 32 * 256 * 48];   // [t][hg][b][jl+16*gate]
__device__ __nv_bfloat16 g_Zh[(size_t)RT * HH];       // h hi [t][b][k]
__device__ __nv_bfloat16 g_Zl[(size_t)RT * HH];       // h lo
__device__ __nv_bfloat16 g_zh0[BB * HH];              // zeros
__device__ unsigned g_cnt[TT * 4];                    // [t][quarter]
struct __align__(128) Bar { unsigned cnt; unsigned gen; unsigned pad[30]; };
__device__ Bar g_bar0;

// ---------------- step smem layout ----------------
#define SM_BIAS 0
#define A_OFF   1024
#define ABUF    32768                    // per chunk buffer: hi 16K + lo 16K
#define BH_OFF  (A_OFF + 4*ABUF)         // 132096
#define BL_OFF  (BH_OFF + 49152)         // 181248
#define SMEM_TC (BL_OFF + 49152)         // 230400

static __device__ __forceinline__ uint32_t s2u(const void* p){
    return (uint32_t)__cvta_generic_to_shared(p);
}
static __device__ __forceinline__ float sigf(float x){
    return __fdividef(1.0f, 1.0f + __expf(-x));
}
static __device__ __forceinline__ void cpa16(uint32_t dst, const void* src){
    asm volatile("cp.async.ca.shared.global [%0], [%1], 16;" :: "r"(dst), "l"(src));
}
static __device__ __forceinline__ void ldsm4(uint32_t a, uint32_t (&r)[4]){
    asm volatile("ldmatrix.sync.aligned.m8n8.x4.shared.b16 {%0,%1,%2,%3}, [%4];"
        : "=r"(r[0]), "=r"(r[1]), "=r"(r[2]), "=r"(r[3]) : "r"(a));
}
static __device__ __forceinline__ void mma16816(float (&d)[4], const uint32_t (&a)[4],
                                                const uint32_t* b){
    asm volatile("mma.sync.aligned.m16n8k16.row.col.f32.bf16.bf16.f32 "
        "{%0,%1,%2,%3}, {%4,%5,%6,%7}, {%8,%9}, {%0,%1,%2,%3};"
        : "+f"(d[0]), "+f"(d[1]), "+f"(d[2]), "+f"(d[3])
        : "r"(a[0]), "r"(a[1]), "r"(a[2]), "r"(a[3]), "r"(b[0]), "r"(b[1]));
}
static __device__ __forceinline__ u64 ffma2(u64 a, u64 b, u64 c){
    u64 d;
    asm("fma.rn.f32x2 %0, %1, %2, %3;" : "=l"(d) : "l"(a), "l"(b), "l"(c));
    return d;
}
static __device__ __forceinline__ float pairsum(u64 v){
    float lo, hi;
    asm("mov.b64 {%0, %1}, %2;" : "=f"(lo), "=f"(hi) : "l"(v));
    return lo + hi;
}

// ---------------- Phase 1: gi (ffma2 compute + smem-staged coalesced writes) ----------
#define GIS 66
#define CST 68
__global__ __launch_bounds__(256) void gi_kernel(const float* __restrict__ X,
                                                 const float* __restrict__ Wih,
                                                 const float* __restrict__ bih)
{
    __shared__ __align__(16) float S[2 * 64 * GIS];   // Xs | Ws, later reused as Cs
    float* Xs = S;
    float* Ws = S + 64*GIS;
    const int r0 = blockIdx.x * 64;
    const int c0 = blockIdx.y * 64;
    const int t  = threadIdx.x;

    #pragma unroll
    for (int j = 0; j < 4; j++){
        int q   = t + 256 * j;
        int row = q >> 4;
        int kq  = q & 15;
        const u64* gx = reinterpret_cast<const u64*>(&X[(size_t)(r0+row)*II + kq*4]);
        u64* px = reinterpret_cast<u64*>(&Xs[row*GIS + kq*4]);
        px[0] = gx[0]; px[1] = gx[1];
        const u64* gw = reinterpret_cast<const u64*>(&Wih[(size_t)(c0+row)*II + kq*4]);
        u64* pw = reinterpret_cast<u64*>(&Ws[row*GIS + kq*4]);
        pw[0] = gw[0]; pw[1] = gw[1];
    }
    __syncthreads();

    const int tm = t & 15;
    const int tn = t >> 4;
    u64 acc[4][4];
    #pragma unroll
    for (int i = 0; i < 4; i++)
        #pragma unroll
        for (int j = 0; j < 4; j++) acc[i][j] = 0ull;

    #pragma unroll 8
    for (int k = 0; k < 64; k += 2){
        u64 a[4], b[4];
        #pragma unroll
        for (int i = 0; i < 4; i++)
            a[i] = *reinterpret_cast<const u64*>(&Xs[(tm+16*i)*GIS + k]);
        #pragma unroll
        for (int j = 0; j < 4; j++)
            b[j] = *reinterpret_cast<const u64*>(&Ws[(tn+16*j)*GIS + k]);
        #pragma unroll
        for (int i = 0; i < 4; i++)
            #pragma unroll
            for (int j = 0; j < 4; j++)
                acc[i][j] = ffma2(a[i], b[j], acc[i][j]);
    }
    __syncthreads();

    // stage to Cs [64 rows][64 cols], stride CST
    float* Cs = S;
    #pragma unroll
    for (int i = 0; i < 4; i++)
        #pragma unroll
        for (int j = 0; j < 4; j++)
            Cs[(tm+16*i)*CST + tn+16*j] = pairsum(acc[i][j]) + bih[c0 + tn + 16*j];
    __syncthreads();

    // coalesced write-out
    const int gate = c0 >> 9;
    const int tt   = r0 >> 8;
    const int b0r  = r0 & 255;
    const int hg0  = (c0 & 511) >> 4;
    float4* go = (float4*)g_gi2;
    #pragma unroll
    for (int q = 0; q < 4; q++){
        int f   = t + 256*q;          // 0..1023
        int row = f >> 4;
        int cc4 = f & 15;             // float4 col index (cc = cc4*4)
        float4 v = *(const float4*)&Cs[row*CST + cc4*4];
        size_t a4 = ((size_t)(tt*32 + hg0 + (cc4 >> 2))*256 + b0r + row)*12
                  + (cc4 & 3) + 4*gate;
        go[a4] = v;
    }
}

// ---------------- Phase 2: persistent HMMA GRU, K-split 8 warps ----------------
__global__ __launch_bounds__(256, 1) void step_tc(const float* __restrict__ Whh,
                                                  const float* __restrict__ bhh)
{
    extern __shared__ __align__(1024) char smem[];
    const uint32_t sb = s2u(smem);
    const int tid  = threadIdx.x;
    const int wid  = tid >> 5, lane = tid & 31;
    const int half = wid >> 2;            // 0: k[0,256), 1: k[256,512)
    const int wm   = wid & 3;             // m-tile
    const int t128 = tid & 127;
    const int bq   = blockIdx.x;          // 0..3 batch quarter
    const int hg   = blockIdx.y;          // 0..31 hidden group
    const int b0   = bq * 64;
    const int h0   = hg * 16;
    const int m0   = wm * 16;
    const int r0   = lane >> 2;
    const int cp   = (lane & 3) * 2;

    float* sBias = (float*)(smem + SM_BIAS);
    if (tid < 48) sBias[tid] = bhh[(tid >> 4)*HH + h0 + (tid & 15)];

    // resident W bf16 split, rows [n][k], 16B-group XOR swizzle
    for (int it = 0; it < 48; it++){
        int idx = tid + 256*it;           // 0..12287 float2 units
        int n   = idx >> 8;               // 0..47
        int k2  = idx & 255;
        int grow = (n >> 4)*HH + h0 + (n & 15);
        float2 w = *(const float2*)&Whh[(size_t)grow*HH + k2*2];
        __nv_bfloat16 wh0 = __float2bfloat16(w.x);
        __nv_bfloat16 wh1 = __float2bfloat16(w.y);
        __nv_bfloat16 wl0 = __float2bfloat16(w.x - __bfloat162float(wh0));
        __nv_bfloat16 wl1 = __float2bfloat16(w.y - __bfloat162float(wh1));
        int k = k2*2, kg = k >> 3;
        uint32_t off = (uint32_t)(n*1024 + ((kg ^ (n & 7)) << 4) + (k & 7)*2);
        __nv_bfloat162 hv(wh0, wh1), lv(wl0, wl1);
        *(uint32_t*)(smem + BH_OFF + off) = *(uint32_t*)&hv;
        *(uint32_t*)(smem + BL_OFF + off) = *(uint32_t*)&lv;
    }

    for (int i = tid; i < TT*4; i += 256) g_cnt[i] = 0;
    __threadfence();
    __syncthreads();
    if (tid == 0){
        unsigned gen;
        asm volatile("ld.acquire.gpu.u32 %0, [%1];" : "=r"(gen) : "l"(&g_bar0.gen) : "memory");
        unsigned arr = atomicAdd(&g_bar0.cnt, 1);
        if (arr == 127){
            atomicExch(&g_bar0.cnt, 0);
            __threadfence();
            atomicAdd(&g_bar0.gen, 1);
        } else {
            unsigned g;
            do { __nanosleep(32);
                 asm volatile("ld.acquire.gpu.u32 %0, [%1];" : "=r"(g) : "l"(&g_bar0.gen) : "memory");
            } while (g == gen);
        }
    }
    __syncthreads();

    float hp[2][2][2];
    #pragma unroll
    for (int a = 0; a < 2; a++)
        #pragma unroll
        for (int b = 0; b < 2; b++)
            #pragma unroll
            for (int c = 0; c < 2; c++) hp[a][b][c] = 0.0f;

    for (int t = 0; t < TT; t++){
        // gi prefetch (epilogue warps only)
        float2 gg[2][3][2];
        if (half == 0){
            #pragma unroll
            for (int rs = 0; rs < 2; rs++){
                int b = b0 + m0 + r0 + 8*rs;
                const float* gp = g_gi2 + ((((size_t)t*32 + hg)*256 + b)*48);
                #pragma unroll
                for (int gate = 0; gate < 3; gate++)
                    #pragma unroll
                    for (int g = 0; g < 2; g++)
                        gg[rs][gate][g] = __ldg((const float2*)(gp + gate*16 + 8*g + cp));
            }
        }

        if (t > 0){
            if (tid == 0){
                const unsigned* cptr = &g_cnt[(t-1)*4 + bq];
                unsigned v;
                do { asm volatile("ld.acquire.gpu.u32 %0, [%1];" : "=r"(v) : "l"(cptr) : "memory");
                     if (v != 32u) __nanosleep(32);
                } while (v != 32u);
            }
            __syncthreads();
        }
        const __nv_bfloat16* Ah = (t == 0) ? g_zh0 : (g_Zh + (size_t)(t-1)*BB*HH);
        const __nv_bfloat16* Al = (t == 0) ? g_zh0 : (g_Zl + (size_t)(t-1)*BB*HH);

        // each half loads its own two K-chunks (k128 each)
        auto loadA = [&](int c){
            uint32_t ab = sb + A_OFF + (uint32_t)(half*2 + c)*ABUF;
            int kbase = half*256 + c*128;
            #pragma unroll
            for (int q = 0; q < 8; q++){
                int idx = t128 + 128*q;          // 0..1023
                int row = idx >> 4, kg = idx & 15;
                uint32_t dst = ab + (uint32_t)(row*256 + ((kg ^ (row & 7)) << 4));
                size_t src = (size_t)(b0+row)*HH + kbase + kg*8;
                cpa16(dst,          Ah + src);
                cpa16(dst + 16384u, Al + src);
            }
            asm volatile("cp.async.commit_group;");
        };
        loadA(0); loadA(1);

        float acc[6][4];
        #pragma unroll
        for (int p = 0; p < 6; p++)
            #pragma unroll
            for (int e = 0; e < 4; e++) acc[p][e] = 0.0f;

        #pragma unroll 1
        for (int c = 0; c < 2; c++){
            if (c == 0) asm volatile("cp.async.wait_group 1;");
            else        asm volatile("cp.async.wait_group 0;");
            if (half == 0) asm volatile("bar.sync 1, 128;" ::: "memory");
            else           asm volatile("bar.sync 2, 128;" ::: "memory");

            uint32_t abuf = sb + A_OFF + (uint32_t)(half*2 + c)*ABUF;
            int rowA = m0 + (lane & 15);
            uint32_t aRowBase = abuf + (uint32_t)(rowA*256);
            #pragma unroll
            for (int s = 0; s < 8; s++){
                uint32_t ah[4], al[4];
                int kgA = s*2 + (lane >> 4);
                uint32_t aoff = aRowBase + (uint32_t)((kgA ^ (lane & 7)) << 4);
                ldsm4(aoff, ah);
                ldsm4(aoff + 16384u, al);
                int kgB = half*32 + c*16 + s*2 + ((lane >> 3) & 1);
                #pragma unroll
                for (int p = 0; p < 3; p++){
                    int rowB = p*16 + (lane & 7) + ((lane >> 4) << 3);
                    uint32_t boff = (uint32_t)(rowB*1024 + ((kgB ^ (lane & 7)) << 4));
                    uint32_t bh[4], bl[4];
                    ldsm4(sb + BH_OFF + boff, bh);
                    ldsm4(sb + BL_OFF + boff, bl);
                    mma16816(acc[2*p],   ah, bh + 0);
                    mma16816(acc[2*p],   al, bh + 0);
                    mma16816(acc[2*p],   ah, bl + 0);
                    mma16816(acc[2*p+1], ah, bh + 2);
                    mma16816(acc[2*p+1], al, bh + 2);
                    mma16816(acc[2*p+1], ah, bl + 2);
                }
            }
        }

        // K-halves reduction via smem overlay on A buffers
        __syncthreads();                      // A dead, both halves done
        float4* red = (float4*)(smem + A_OFF) + (size_t)(wm*32 + lane)*7;
        if (half == 1){
            red[0] = make_float4(acc[0][0], acc[0][1], acc[0][2], acc[0][3]);
            red[1] = make_float4(acc[1][0], acc[1][1], acc[1][2], acc[1][3]);
            red[2] = make_float4(acc[2][0], acc[2][1], acc[2][2], acc[2][3]);
            red[3] = make_float4(acc[3][0], acc[3][1], acc[3][2], acc[3][3]);
            red[4] = make_float4(acc[4][0], acc[4][1], acc[4][2], acc[4][3]);
            red[5] = make_float4(acc[5][0], acc[5][1], acc[5][2], acc[5][3]);
        }
        __syncthreads();
        if (half == 0){
            #pragma unroll
            for (int p = 0; p < 6; p++){
                float4 v = red[p];
                acc[p][0] += v.x; acc[p][1] += v.y; acc[p][2] += v.z; acc[p][3] += v.w;
            }
            // fused gate epilogue
            #pragma unroll
            for (int rs = 0; rs < 2; rs++){
                int b = b0 + m0 + r0 + 8*rs;
                uint32_t hw[2], lw[2];
                #pragma unroll
                for (int g = 0; g < 2; g++){
                    float hn2[2];
                    #pragma unroll
                    for (int e = 0; e < 2; e++){
                        int jl = 8*g + cp + e;
                        float pr = acc[0+g][2*rs+e] + sBias[jl];
                        float pz = acc[2+g][2*rs+e] + sBias[16+jl];
                        float pn = acc[4+g][2*rs+e] + sBias[32+jl];
                        const float* gr = (const float*)&gg[rs][0][g];
                        const float* gz = (const float*)&gg[rs][1][g];
                        const float* gn = (const float*)&gg[rs][2][g];
                        float r  = sigf(gr[e] + pr);
                        float z  = sigf(gz[e] + pz);
                        float nn = tanhf(gn[e] + r * pn);
                        float hn = (1.0f - z) * nn + z * hp[rs][g][e];
                        hp[rs][g][e] = hn;
                        hn2[e] = hn;
                    }
                    __nv_bfloat16 a0 = __float2bfloat16(hn2[0]);
                    __nv_bfloat16 a1 = __float2bfloat16(hn2[1]);
                    __nv_bfloat16 c0 = __float2bfloat16(hn2[0] - __bfloat162float(a0));
                    __nv_bfloat16 c1 = __float2bfloat16(hn2[1] - __bfloat162float(a1));
                    __nv_bfloat162 hv(a0, a1), lv(c0, c1);
                    hw[g] = *(uint32_t*)&hv;
                    lw[g] = *(uint32_t*)&lv;
                }
                size_t o = ((size_t)t*BB + b)*HH + h0 + cp;
                *(uint32_t*)(g_Zh + o)     = hw[0];
                *(uint32_t*)(g_Zh + o + 8) = hw[1];
                *(uint32_t*)(g_Zl + o)     = lw[0];
                *(uint32_t*)(g_Zl + o + 8) = lw[1];
            }
            __threadfence();
        }

        __syncthreads();
        if (tid == 0){
            asm volatile("red.release.gpu.global.add.u32 [%0], %1;"
                         :: "l"(&g_cnt[t*4 + bq]), "r"(1u) : "memory");
        }
    }
}

// ---------------- Phase 3: V = bias + (Zh+Zl) . vw ----------------
__global__ __launch_bounds__(256) void value_kernel(const float* __restrict__ vw,
                                                    const float* __restrict__ bias,
                                                    float* __restrict__ out)
{
    int warp = (blockIdx.x * 256 + threadIdx.x) >> 5;
    int lane = threadIdx.x & 31;
    const __nv_bfloat16* zh = g_Zh + (size_t)warp * HH;
    const __nv_bfloat16* zl = g_Zl + (size_t)warp * HH;
    float s = 0.0f;
    #pragma unroll
    for (int i = 0; i < 4; i++){
        int idx = i*128 + lane*4;
        uint2 ah = *(const uint2*)(zh + idx);
        uint2 al = *(const uint2*)(zl + idx);
        float4 wv = *(const float4*)(&vw[idx]);
        __nv_bfloat162 h0 = *(__nv_bfloat162*)&ah.x;
        __nv_bfloat162 h1 = *(__nv_bfloat162*)&ah.y;
        __nv_bfloat162 l0 = *(__nv_bfloat162*)&al.x;
        __nv_bfloat162 l1 = *(__nv_bfloat162*)&al.y;
        s += (__bfloat162float(h0.x) + __bfloat162float(l0.x)) * wv.x;
        s += (__bfloat162float(h0.y) + __bfloat162float(l0.y)) * wv.y;
        s += (__bfloat162float(h1.x) + __bfloat162float(l1.x)) * wv.z;
        s += (__bfloat162float(h1.y) + __bfloat162float(l1.y)) * wv.w;
    }
    #pragma unroll
    for (int o = 16; o > 0; o >>= 1)
        s += __shfl_xor_sync(0xFFFFFFFFu, s, o);
    if (lane == 0) out[warp] = s + bias[0];
}

extern "C" void kernel_launch(void* const* d_in, const int* in_sizes, int n_in,
                              void* d_out, int out_size)
{
    const float* X    = (const float*)d_in[0];
    const float* Wih  = (const float*)d_in[1];
    const float* Whh  = (const float*)d_in[2];
    const float* bih  = (const float*)d_in[3];
    const float* bhh  = (const float*)d_in[4];
    const float* vw   = (const float*)d_in[5];
    const float* bias = (const float*)d_in[6];
    float* out = (float*)d_out;

    static int smem_set = 0;
    if (!smem_set){
        cudaFuncSetAttribute(step_tc, cudaFuncAttributeMaxDynamicSharedMemorySize, SMEM_TC);
        smem_set = 1;
    }

    dim3 ggi(RT/64, G3/64);
    gi_kernel<<<ggi, 256>>>(X, Wih, bih);

    step_tc<<<dim3(4, 32), 256, SMEM_TC>>>(Whh, bhh);

    value_kernel<<<RT/8, 256>>>(vw, bias, out);
}

// round 12
// speedup vs baseline: 2.9107x; 1.1478x over previous
#include <cuda_runtime.h>
#include <cuda_fp16.h>
#include <cstdint>

#define TT 512
#define BB 256
#define II 64
#define HH 512
#define G3 1536
#define RT (TT*BB)

typedef unsigned long long u64;

// ---------------- scratch ----------------
__device__ float g_gi2[(size_t)TT * 32 * 256 * 48];   // [t][hg][b][jl+16*gate]
__device__ __half g_Zh[(size_t)RT * HH];              // h hi [t][b][k]
__device__ __half g_Zl[(size_t)RT * HH];              // h lo
__device__ __half g_zh0[BB * HH];                     // zeros
__device__ unsigned g_cnt[TT * 16];                   // [t][bq][kgroup]
struct __align__(128) Bar { unsigned cnt; unsigned gen; unsigned pad[30]; };
__device__ Bar g_bar0;

// ---------------- step smem layout ----------------
#define SM_BIAS 0
#define A_OFF   1024
#define ABUF    32768                    // per chunk buffer: hi 16K + lo 16K
#define BH_OFF  (A_OFF + 4*ABUF)         // 132096
#define SMEM_TC (BH_OFF + 49152)         // 181248

static __device__ __forceinline__ uint32_t s2u(const void* p){
    return (uint32_t)__cvta_generic_to_shared(p);
}
static __device__ __forceinline__ float sigf(float x){
    return __fdividef(1.0f, 1.0f + __expf(-x));
}
static __device__ __forceinline__ void cpa16(uint32_t dst, const void* src){
    asm volatile("cp.async.ca.shared.global [%0], [%1], 16;" :: "r"(dst), "l"(src));
}
static __device__ __forceinline__ void ldsm4(uint32_t a, uint32_t (&r)[4]){
    asm volatile("ldmatrix.sync.aligned.m8n8.x4.shared.b16 {%0,%1,%2,%3}, [%4];"
        : "=r"(r[0]), "=r"(r[1]), "=r"(r[2]), "=r"(r[3]) : "r"(a));
}
static __device__ __forceinline__ void mma16816(float (&d)[4], const uint32_t (&a)[4],
                                                const uint32_t* b){
    asm volatile("mma.sync.aligned.m16n8k16.row.col.f32.f16.f16.f32 "
        "{%0,%1,%2,%3}, {%4,%5,%6,%7}, {%8,%9}, {%0,%1,%2,%3};"
        : "+f"(d[0]), "+f"(d[1]), "+f"(d[2]), "+f"(d[3])
        : "r"(a[0]), "r"(a[1]), "r"(a[2]), "r"(a[3]), "r"(b[0]), "r"(b[1]));
}
static __device__ __forceinline__ u64 ffma2(u64 a, u64 b, u64 c){
    u64 d;
    asm("fma.rn.f32x2 %0, %1, %2, %3;" : "=l"(d) : "l"(a), "l"(b), "l"(c));
    return d;
}
static __device__ __forceinline__ float pairsum(u64 v){
    float lo, hi;
    asm("mov.b64 {%0, %1}, %2;" : "=f"(lo), "=f"(hi) : "l"(v));
    return lo + hi;
}

// ---------------- Phase 1: gi (ffma2 compute + smem-staged coalesced writes) ----------
#define GIS 66
#define CST 68
__global__ __launch_bounds__(256) void gi_kernel(const float* __restrict__ X,
                                                 const float* __restrict__ Wih,
                                                 const float* __restrict__ bih)
{
    __shared__ __align__(16) float S[2 * 64 * GIS];
    float* Xs = S;
    float* Ws = S + 64*GIS;
    const int r0 = blockIdx.x * 64;
    const int c0 = blockIdx.y * 64;
    const int t  = threadIdx.x;

    #pragma unroll
    for (int j = 0; j < 4; j++){
        int q   = t + 256 * j;
        int row = q >> 4;
        int kq  = q & 15;
        const u64* gx = reinterpret_cast<const u64*>(&X[(size_t)(r0+row)*II + kq*4]);
        u64* px = reinterpret_cast<u64*>(&Xs[row*GIS + kq*4]);
        px[0] = gx[0]; px[1] = gx[1];
        const u64* gw = reinterpret_cast<const u64*>(&Wih[(size_t)(c0+row)*II + kq*4]);
        u64* pw = reinterpret_cast<u64*>(&Ws[row*GIS + kq*4]);
        pw[0] = gw[0]; pw[1] = gw[1];
    }
    __syncthreads();

    const int tm = t & 15;
    const int tn = t >> 4;
    u64 acc[4][4];
    #pragma unroll
    for (int i = 0; i < 4; i++)
        #pragma unroll
        for (int j = 0; j < 4; j++) acc[i][j] = 0ull;

    #pragma unroll 8
    for (int k = 0; k < 64; k += 2){
        u64 a[4], b[4];
        #pragma unroll
        for (int i = 0; i < 4; i++)
            a[i] = *reinterpret_cast<const u64*>(&Xs[(tm+16*i)*GIS + k]);
        #pragma unroll
        for (int j = 0; j < 4; j++)
            b[j] = *reinterpret_cast<const u64*>(&Ws[(tn+16*j)*GIS + k]);
        #pragma unroll
        for (int i = 0; i < 4; i++)
            #pragma unroll
            for (int j = 0; j < 4; j++)
                acc[i][j] = ffma2(a[i], b[j], acc[i][j]);
    }
    __syncthreads();

    float* Cs = S;
    #pragma unroll
    for (int i = 0; i < 4; i++)
        #pragma unroll
        for (int j = 0; j < 4; j++)
            Cs[(tm+16*i)*CST + tn+16*j] = pairsum(acc[i][j]) + bih[c0 + tn + 16*j];
    __syncthreads();

    const int gate = c0 >> 9;
    const int tt   = r0 >> 8;
    const int b0r  = r0 & 255;
    const int hg0  = (c0 & 511) >> 4;
    float4* go = (float4*)g_gi2;
    #pragma unroll
    for (int q = 0; q < 4; q++){
        int f   = t + 256*q;
        int row = f >> 4;
        int cc4 = f & 15;
        float4 v = *(const float4*)&Cs[row*CST + cc4*4];
        size_t a4 = ((size_t)(tt*32 + hg0 + (cc4 >> 2))*256 + b0r + row)*12
                  + (cc4 & 3) + 4*gate;
        go[a4] = v;
    }
}

// ---------------- Phase 2: persistent HMMA GRU, fp16 2-term, K-split ----------------
__global__ __launch_bounds__(256, 1) void step_tc(const float* __restrict__ Whh,
                                                  const float* __restrict__ bhh)
{
    extern __shared__ __align__(1024) char smem[];
    const uint32_t sb = s2u(smem);
    const int tid  = threadIdx.x;
    const int wid  = tid >> 5, lane = tid & 31;
    const int half = wid >> 2;            // 0: k[0,256), 1: k[256,512)
    const int wm   = wid & 3;             // m-tile
    const int t128 = tid & 127;
    const int bq   = blockIdx.x;          // batch quarter
    const int hg   = blockIdx.y;          // hidden group
    const int b0   = bq * 64;
    const int h0   = hg * 16;
    const int m0   = wm * 16;
    const int r0   = lane >> 2;
    const int cp   = (lane & 3) * 2;

    float* sBias = (float*)(smem + SM_BIAS);
    if (tid < 48) sBias[tid] = bhh[(tid >> 4)*HH + h0 + (tid & 15)];

    // resident W fp16, rows [n][k], 16B-group XOR swizzle
    for (int it = 0; it < 48; it++){
        int idx = tid + 256*it;           // 0..12287 float2 units
        int n   = idx >> 8;
        int k2  = idx & 255;
        int grow = (n >> 4)*HH + h0 + (n & 15);
        float2 w = *(const float2*)&Whh[(size_t)grow*HH + k2*2];
        __half2 hv = __halves2half2(__float2half_rn(w.x), __float2half_rn(w.y));
        int k = k2*2, kg = k >> 3;
        uint32_t off = (uint32_t)(n*1024 + ((kg ^ (n & 7)) << 4) + (k & 7)*2);
        *(uint32_t*)(smem + BH_OFF + off) = *(uint32_t*)&hv;
    }

    for (int i = tid; i < TT*16; i += 256) g_cnt[i] = 0;
    __threadfence();
    __syncthreads();
    if (tid == 0){
        unsigned gen;
        asm volatile("ld.acquire.gpu.u32 %0, [%1];" : "=r"(gen) : "l"(&g_bar0.gen) : "memory");
        unsigned arr = atomicAdd(&g_bar0.cnt, 1);
        if (arr == 127){
            atomicExch(&g_bar0.cnt, 0);
            __threadfence();
            atomicAdd(&g_bar0.gen, 1);
        } else {
            unsigned g;
            do { __nanosleep(32);
                 asm volatile("ld.acquire.gpu.u32 %0, [%1];" : "=r"(g) : "l"(&g_bar0.gen) : "memory");
            } while (g == gen);
        }
    }
    __syncthreads();

    float hp[2][2][2];
    #pragma unroll
    for (int a = 0; a < 2; a++)
        #pragma unroll
        for (int b = 0; b < 2; b++)
            #pragma unroll
            for (int c = 0; c < 2; c++) hp[a][b][c] = 0.0f;

    for (int t = 0; t < TT; t++){
        float2 gg[2][3][2];
        if (half == 0){
            #pragma unroll
            for (int rs = 0; rs < 2; rs++){
                int b = b0 + m0 + r0 + 8*rs;
                const float* gp = g_gi2 + ((((size_t)t*32 + hg)*256 + b)*48);
                #pragma unroll
                for (int gate = 0; gate < 3; gate++)
                    #pragma unroll
                    for (int g = 0; g < 2; g++)
                        gg[rs][gate][g] = __ldg((const float2*)(gp + gate*16 + 8*g + cp));
            }
        }

        const __half* Ah = (t == 0) ? g_zh0 : (g_Zh + (size_t)(t-1)*BB*HH);
        const __half* Al = (t == 0) ? g_zh0 : (g_Zl + (size_t)(t-1)*BB*HH);

        // wait producers of kgroup, then load chunk c (this half's threads only)
        auto waitgrp = [&](int c){
            if (t == 0) return;
            const unsigned* fp = &g_cnt[(size_t)(t-1)*16 + bq*4 + half*2 + c];
            if (lane == 0){
                unsigned v;
                do { asm volatile("ld.acquire.gpu.u32 %0, [%1];" : "=r"(v) : "l"(fp) : "memory");
                     if (v != 8u) __nanosleep(16);
                } while (v != 8u);
            }
            __syncwarp();
        };
        auto loadA = [&](int c){
            uint32_t ab = sb + A_OFF + (uint32_t)(half*2 + c)*ABUF;
            int kbase = half*256 + c*128;
            #pragma unroll
            for (int q = 0; q < 8; q++){
                int idx = t128 + 128*q;
                int row = idx >> 4, kg = idx & 15;
                uint32_t dst = ab + (uint32_t)(row*256 + ((kg ^ (row & 7)) << 4));
                size_t src = (size_t)(b0+row)*HH + kbase + kg*8;
                cpa16(dst,          Ah + src);
                cpa16(dst + 16384u, Al + src);
            }
            asm volatile("cp.async.commit_group;");
        };
        waitgrp(0); loadA(0);
        waitgrp(1); loadA(1);

        float acc[6][4];
        #pragma unroll
        for (int p = 0; p < 6; p++)
            #pragma unroll
            for (int e = 0; e < 4; e++) acc[p][e] = 0.0f;

        #pragma unroll 1
        for (int c = 0; c < 2; c++){
            if (c == 0) asm volatile("cp.async.wait_group 1;");
            else        asm volatile("cp.async.wait_group 0;");
            if (half == 0) asm volatile("bar.sync 1, 128;" ::: "memory");
            else           asm volatile("bar.sync 2, 128;" ::: "memory");

            uint32_t abuf = sb + A_OFF + (uint32_t)(half*2 + c)*ABUF;
            int rowA = m0 + (lane & 15);
            uint32_t aRowBase = abuf + (uint32_t)(rowA*256);
            #pragma unroll
            for (int s = 0; s < 8; s++){
                uint32_t ah[4], al[4];
                int kgA = s*2 + (lane >> 4);
                uint32_t aoff = aRowBase + (uint32_t)((kgA ^ (lane & 7)) << 4);
                ldsm4(aoff, ah);
                ldsm4(aoff + 16384u, al);
                int kgB = half*32 + c*16 + s*2 + ((lane >> 3) & 1);
                #pragma unroll
                for (int p = 0; p < 3; p++){
                    int rowB = p*16 + (lane & 7) + ((lane >> 4) << 3);
                    uint32_t boff = (uint32_t)(rowB*1024 + ((kgB ^ (lane & 7)) << 4));
                    uint32_t bh[4];
                    ldsm4(sb + BH_OFF + boff, bh);
                    mma16816(acc[2*p],   ah, bh + 0);
                    mma16816(acc[2*p],   al, bh + 0);
                    mma16816(acc[2*p+1], ah, bh + 2);
                    mma16816(acc[2*p+1], al, bh + 2);
                }
            }
        }

        // K-halves reduction via smem overlay on A buffers
        __syncthreads();
        float4* red = (float4*)(smem + A_OFF) + (size_t)(wm*32 + lane)*7;
        if (half == 1){
            red[0] = make_float4(acc[0][0], acc[0][1], acc[0][2], acc[0][3]);
            red[1] = make_float4(acc[1][0], acc[1][1], acc[1][2], acc[1][3]);
            red[2] = make_float4(acc[2][0], acc[2][1], acc[2][2], acc[2][3]);
            red[3] = make_float4(acc[3][0], acc[3][1], acc[3][2], acc[3][3]);
            red[4] = make_float4(acc[4][0], acc[4][1], acc[4][2], acc[4][3]);
            red[5] = make_float4(acc[5][0], acc[5][1], acc[5][2], acc[5][3]);
        }
        __syncthreads();
        if (half == 0){
            #pragma unroll
            for (int p = 0; p < 6; p++){
                float4 v = red[p];
                acc[p][0] += v.x; acc[p][1] += v.y; acc[p][2] += v.z; acc[p][3] += v.w;
            }
            #pragma unroll
            for (int rs = 0; rs < 2; rs++){
                int b = b0 + m0 + r0 + 8*rs;
                uint32_t hw[2], lw[2];
                #pragma unroll
                for (int g = 0; g < 2; g++){
                    float hn2[2];
                    #pragma unroll
                    for (int e = 0; e < 2; e++){
                        int jl = 8*g + cp + e;
                        float pr = acc[0+g][2*rs+e] + sBias[jl];
                        float pz = acc[2+g][2*rs+e] + sBias[16+jl];
                        float pn = acc[4+g][2*rs+e] + sBias[32+jl];
                        const float* gr = (const float*)&gg[rs][0][g];
                        const float* gz = (const float*)&gg[rs][1][g];
                        const float* gn = (const float*)&gg[rs][2][g];
                        float r  = sigf(gr[e] + pr);
                        float z  = sigf(gz[e] + pz);
                        float nn = tanhf(gn[e] + r * pn);
                        float hn = (1.0f - z) * nn + z * hp[rs][g][e];
                        hp[rs][g][e] = hn;
                        hn2[e] = hn;
                    }
                    __half a0 = __float2half_rn(hn2[0]);
                    __half a1 = __float2half_rn(hn2[1]);
                    __half c0 = __float2half_rn(hn2[0] - __half2float(a0));
                    __half c1 = __float2half_rn(hn2[1] - __half2float(a1));
                    __half2 hv = __halves2half2(a0, a1);
                    __half2 lv = __halves2half2(c0, c1);
                    hw[g] = *(uint32_t*)&hv;
                    lw[g] = *(uint32_t*)&lv;
                }
                size_t o = ((size_t)t*BB + b)*HH + h0 + cp;
                *(uint32_t*)(g_Zh + o)     = hw[0];
                *(uint32_t*)(g_Zh + o + 8) = hw[1];
                *(uint32_t*)(g_Zl + o)     = lw[0];
                *(uint32_t*)(g_Zl + o + 8) = lw[1];
            }
        }

        __syncthreads();
        if (tid == 0){
            asm volatile("red.release.gpu.global.add.u32 [%0], %1;"
                         :: "l"(&g_cnt[(size_t)t*16 + bq*4 + (hg >> 3)]), "r"(1u) : "memory");
        }
    }
}

// ---------------- Phase 3: V = bias + (Zh+Zl) . vw ----------------
__global__ __launch_bounds__(256) void value_kernel(const float* __restrict__ vw,
                                                    const float* __restrict__ bias,
                                                    float* __restrict__ out)
{
    int warp = (blockIdx.x * 256 + threadIdx.x) >> 5;
    int lane = threadIdx.x & 31;
    const __half* zh = g_Zh + (size_t)warp * HH;
    const __half* zl = g_Zl + (size_t)warp * HH;
    float s = 0.0f;
    #pragma unroll
    for (int i = 0; i < 4; i++){
        int idx = i*128 + lane*4;
        uint2 ah = *(const uint2*)(zh + idx);
        uint2 al = *(const uint2*)(zl + idx);
        float4 wv = *(const float4*)(&vw[idx]);
        __half2 h0 = *(__half2*)&ah.x;
        __half2 h1 = *(__half2*)&ah.y;
        __half2 l0 = *(__half2*)&al.x;
        __half2 l1 = *(__half2*)&al.y;
        s += (__half2float(h0.x) + __half2float(l0.x)) * wv.x;
        s += (__half2float(h0.y) + __half2float(l0.y)) * wv.y;
        s += (__half2float(h1.x) + __half2float(l1.x)) * wv.z;
        s += (__half2float(h1.y) + __half2float(l1.y)) * wv.w;
    }
    #pragma unroll
    for (int o = 16; o > 0; o >>= 1)
        s += __shfl_xor_sync(0xFFFFFFFFu, s, o);
    if (lane == 0) out[warp] = s + bias[0];
}

extern "C" void kernel_launch(void* const* d_in, const int* in_sizes, int n_in,
                              void* d_out, int out_size)
{
    const float* X    = (const float*)d_in[0];
    const float* Wih  = (const float*)d_in[1];
    const float* Whh  = (const float*)d_in[2];
    const float* bih  = (const float*)d_in[3];
    const float* bhh  = (const float*)d_in[4];
    const float* vw   = (const float*)d_in[5];
    const float* bias = (const float*)d_in[6];
    float* out = (float*)d_out;

    static int smem_set = 0;
    if (!smem_set){
        cudaFuncSetAttribute(step_tc, cudaFuncAttributeMaxDynamicSharedMemorySize, SMEM_TC);
        smem_set = 1;
    }

    dim3 ggi(RT/64, G3/64);
    gi_kernel<<<ggi, 256>>>(X, Wih, bih);

    step_tc<<<dim3(4, 32), 256, SMEM_TC>>>(Whh, bhh);

    value_kernel<<<RT/8, 256>>>(vw, bias, out);
}

// round 15
// speedup vs baseline: 3.0354x; 1.0428x over previous
#include <cuda_runtime.h>
#include <cuda_fp16.h>
#include <cstdint>

#define TT 512
#define BB 256
#define II 64
#define HH 512
#define G3 1536
#define RT (TT*BB)

typedef unsigned long long u64;

// ---------------- scratch ----------------
__device__ float g_gi2[(size_t)TT * 32 * 256 * 48];   // [t][hg][b][jl+16*gate]
__device__ __half g_Xh[(size_t)RT * II];              // X fp16 hi
__device__ __half g_Xl[(size_t)RT * II];              // X fp16 lo
__device__ __half g_Wh[(size_t)G3 * II];              // Wih fp16 hi
__device__ __half g_Wl[(size_t)G3 * II];              // Wih fp16 lo
__device__ __half g_Zh[(size_t)RT * HH];              // h hi [t][b][k]
__device__ __half g_Zl[(size_t)RT * HH];              // h lo
__device__ __half g_zh0[BB * HH];                     // zeros
__device__ unsigned g_cnt[TT * 16];                   // [t][bq][kgroup]
struct __align__(128) Bar { unsigned cnt; unsigned gen; unsigned pad[30]; };
__device__ Bar g_bar0;

// ---------------- step smem layout ----------------
#define SM_BIAS 0
#define A_OFF   1024
#define ABUF    32768
#define BH_OFF  (A_OFF + 4*ABUF)         // 132096
#define SMEM_TC (BH_OFF + 49152)         // 181248

// ---------------- gi smem layout ----------------
#define GXH 0
#define GXL 16384
#define GWH 32768
#define GWL 40960
#define SMEM_GI 49152

static __device__ __forceinline__ uint32_t s2u(const void* p){
    return (uint32_t)__cvta_generic_to_shared(p);
}
static __device__ __forceinline__ float sigf(float x){
    return __fdividef(1.0f, 1.0f + __expf(-x));
}
static __device__ __forceinline__ void cpa16(uint32_t dst, const void* src){
    asm volatile("cp.async.ca.shared.global [%0], [%1], 16;" :: "r"(dst), "l"(src));
}
static __device__ __forceinline__ void ldsm4(uint32_t a, uint32_t (&r)[4]){
    asm volatile("ldmatrix.sync.aligned.m8n8.x4.shared.b16 {%0,%1,%2,%3}, [%4];"
        : "=r"(r[0]), "=r"(r[1]), "=r"(r[2]), "=r"(r[3]) : "r"(a));
}
static __device__ __forceinline__ void mma16816(float (&d)[4], const uint32_t (&a)[4],
                                                const uint32_t* b){
    asm volatile("mma.sync.aligned.m16n8k16.row.col.f32.f16.f16.f32 "
        "{%0,%1,%2,%3}, {%4,%5,%6,%7}, {%8,%9}, {%0,%1,%2,%3};"
        : "+f"(d[0]), "+f"(d[1]), "+f"(d[2]), "+f"(d[3])
        : "r"(a[0]), "r"(a[1]), "r"(a[2]), "r"(a[3]), "r"(b[0]), "r"(b[1]));
}

// ---------------- Phase 0: fp16 hi/lo conversion of X and Wih ----------------
__global__ __launch_bounds__(256) void cvt_kernel(const float* __restrict__ X,
                                                  const float* __restrict__ Wih)
{
    int bx = blockIdx.x;
    const float* src; __half *dh, *dl; size_t i;
    if (bx < 8192){
        i = ((size_t)bx*256 + threadIdx.x)*4;
        src = X; dh = g_Xh; dl = g_Xl;
    } else {
        i = ((size_t)(bx-8192)*256 + threadIdx.x)*4;
        if (i >= (size_t)G3*II) return;
        src = Wih; dh = g_Wh; dl = g_Wl;
    }
    float4 v = *(const float4*)(src + i);
    __half h0 = __float2half_rn(v.x), h1 = __float2half_rn(v.y);
    __half h2 = __float2half_rn(v.z), h3 = __float2half_rn(v.w);
    __half l0 = __float2half_rn(v.x - __half2float(h0));
    __half l1 = __float2half_rn(v.y - __half2float(h1));
    __half l2 = __float2half_rn(v.z - __half2float(h2));
    __half l3 = __float2half_rn(v.w - __half2float(h3));
    __half2 hA = __halves2half2(h0, h1), hB = __halves2half2(h2, h3);
    __half2 lA = __halves2half2(l0, l1), lB = __halves2half2(l2, l3);
    *(uint2*)(dh + i) = make_uint2(*(uint32_t*)&hA, *(uint32_t*)&hB);
    *(uint2*)(dl + i) = make_uint2(*(uint32_t*)&lA, *(uint32_t*)&lB);
}

// ---------------- Phase 1: gi via HMMA (fp16 3-term) ----------------
#define CST 68
__global__ __launch_bounds__(256) void gi_hmma(const float* __restrict__ bih)
{
    extern __shared__ __align__(1024) char smem[];
    const uint32_t sb = s2u(smem);
    const int tid = threadIdx.x;
    const int wid = tid >> 5, lane = tid & 31;
    const int wm2 = wid >> 1, wn = wid & 1;
    const int r0 = blockIdx.x * 128;
    const int c0 = blockIdx.y * 64;

    #pragma unroll
    for (int q = 0; q < 4; q++){
        int idx = tid + 256*q;            // 0..1023
        int row = idx >> 3, kg = idx & 7;
        uint32_t off = (uint32_t)(row*128 + ((kg ^ (row & 7)) << 4));
        size_t src = (size_t)(r0+row)*II + kg*8;
        cpa16(sb + GXH + off, g_Xh + src);
        cpa16(sb + GXL + off, g_Xl + src);
    }
    #pragma unroll
    for (int q = 0; q < 2; q++){
        int idx = tid + 256*q;            // 0..511
        int n = idx >> 3, kg = idx & 7;
        uint32_t off = (uint32_t)(n*128 + ((kg ^ (n & 7)) << 4));
        size_t src = (size_t)(c0+n)*II + kg*8;
        cpa16(sb + GWH + off, g_Wh + src);
        cpa16(sb + GWL + off, g_Wl + src);
    }
    asm volatile("cp.async.commit_group;");
    asm volatile("cp.async.wait_group 0;");
    __syncthreads();

    float acc[2][4][4];
    #pragma unroll
    for (int f = 0; f < 2; f++)
        #pragma unroll
        for (int n8 = 0; n8 < 4; n8++)
            #pragma unroll
            for (int e = 0; e < 4; e++) acc[f][n8][e] = 0.0f;

    #pragma unroll
    for (int ks = 0; ks < 4; ks++){
        uint32_t ah[2][4], al[2][4];
        #pragma unroll
        for (int f = 0; f < 2; f++){
            int rowA = wm2*32 + f*16 + (lane & 15);
            int kgA  = ks*2 + (lane >> 4);
            uint32_t off = (uint32_t)(rowA*128 + ((kgA ^ (rowA & 7)) << 4));
            ldsm4(sb + GXH + off, ah[f]);
            ldsm4(sb + GXL + off, al[f]);
        }
        #pragma unroll
        for (int nf = 0; nf < 2; nf++){
            int rowB = wn*32 + nf*16 + (lane & 7) + ((lane >> 4) << 3);
            int kgB  = ks*2 + ((lane >> 3) & 1);
            uint32_t boff = (uint32_t)(rowB*128 + ((kgB ^ (rowB & 7)) << 4));
            uint32_t bh[4], bl[4];
            ldsm4(sb + GWH + boff, bh);
            ldsm4(sb + GWL + boff, bl);
            #pragma unroll
            for (int f = 0; f < 2; f++){
                mma16816(acc[f][nf*2],   ah[f], bh + 0);
                mma16816(acc[f][nf*2],   al[f], bh + 0);
                mma16816(acc[f][nf*2],   ah[f], bl + 0);
                mma16816(acc[f][nf*2+1], ah[f], bh + 2);
                mma16816(acc[f][nf*2+1], al[f], bh + 2);
                mma16816(acc[f][nf*2+1], ah[f], bl + 2);
            }
        }
    }
    __syncthreads();

    float* Cs = (float*)smem;
    #pragma unroll
    for (int f = 0; f < 2; f++)
        #pragma unroll
        for (int n8 = 0; n8 < 4; n8++){
            int R = wm2*32 + f*16 + (lane >> 2);
            int C = wn*32 + n8*8 + (lane & 3)*2;
            Cs[R*CST + C]       = acc[f][n8][0];
            Cs[R*CST + C + 1]   = acc[f][n8][1];
            Cs[(R+8)*CST + C]   = acc[f][n8][2];
            Cs[(R+8)*CST + C+1] = acc[f][n8][3];
        }
    __syncthreads();

    const int gate = c0 >> 9;
    const int tt   = r0 >> 8;
    const int b0r  = r0 & 255;
    const int hg0  = (c0 & 511) >> 4;
    float4* go = (float4*)g_gi2;
    #pragma unroll
    for (int q = 0; q < 8; q++){
        int f   = tid + 256*q;            // 0..2047
        int row = f >> 4;
        int cc4 = f & 15;
        float4 v  = *(const float4*)&Cs[row*CST + cc4*4];
        float4 bv = *(const float4*)&bih[c0 + cc4*4];
        v.x += bv.x; v.y += bv.y; v.z += bv.z; v.w += bv.w;
        size_t a4 = ((size_t)(tt*32 + hg0 + (cc4 >> 2))*256 + b0r + row)*12
                  + (cc4 & 3) + 4*gate;
        go[a4] = v;
    }
}

// ---------------- Phase 2: persistent HMMA GRU, fp16 2-term, K-split ----------------
__global__ __launch_bounds__(256, 1) void step_tc(const float* __restrict__ Whh,
                                                  const float* __restrict__ bhh)
{
    extern __shared__ __align__(1024) char smem[];
    const uint32_t sb = s2u(smem);
    const int tid  = threadIdx.x;
    const int wid  = tid >> 5, lane = tid & 31;
    const int half = wid >> 2;            // 0: k[0,256), 1: k[256,512)
    const int wm   = wid & 3;
    const int t128 = tid & 127;
    const int bq   = blockIdx.x;
    const int hg   = blockIdx.y;
    const int b0   = bq * 64;
    const int h0   = hg * 16;
    const int m0   = wm * 16;
    const int r0   = lane >> 2;
    const int cp   = (lane & 3) * 2;
    const int bmine = b0 + m0 + r0 + 8*half;

    float* sBias = (float*)(smem + SM_BIAS);
    if (tid < 48) sBias[tid] = bhh[(tid >> 4)*HH + h0 + (tid & 15)];

    for (int it = 0; it < 48; it++){
        int idx = tid + 256*it;
        int n   = idx >> 8;
        int k2  = idx & 255;
        int grow = (n >> 4)*HH + h0 + (n & 15);
        float2 w = *(const float2*)&Whh[(size_t)grow*HH + k2*2];
        __half2 hv = __halves2half2(__float2half_rn(w.x), __float2half_rn(w.y));
        int k = k2*2, kg = k >> 3;
        uint32_t off = (uint32_t)(n*1024 + ((kg ^ (n & 7)) << 4) + (k & 7)*2);
        *(uint32_t*)(smem + BH_OFF + off) = *(uint32_t*)&hv;
    }

    for (int i = tid; i < TT*16; i += 256) g_cnt[i] = 0;
    __threadfence();
    __syncthreads();
    if (tid == 0){
        unsigned gen;
        asm volatile("ld.acquire.gpu.u32 %0, [%1];" : "=r"(gen) : "l"(&g_bar0.gen) : "memory");
        unsigned arr = atomicAdd(&g_bar0.cnt, 1);
        if (arr == 127){
            atomicExch(&g_bar0.cnt, 0);
            __threadfence();
            atomicAdd(&g_bar0.gen, 1);
        } else {
            unsigned g;
            do { __nanosleep(32);
                 asm volatile("ld.acquire.gpu.u32 %0, [%1];" : "=r"(g) : "l"(&g_bar0.gen) : "memory");
            } while (g == gen);
        }
    }
    __syncthreads();

    float hp[2][2];
    #pragma unroll
    for (int g = 0; g < 2; g++)
        #pragma unroll
        for (int e = 0; e < 2; e++) hp[g][e] = 0.0f;

    for (int t = 0; t < TT; t++){
        float2 gg[3][2];
        {
            const float* gp = g_gi2 + ((((size_t)t*32 + hg)*256 + bmine)*48);
            #pragma unroll
            for (int gate = 0; gate < 3; gate++)
                #pragma unroll
                for (int g = 0; g < 2; g++)
                    gg[gate][g] = __ldg((const float2*)(gp + gate*16 + 8*g + cp));
        }

        const __half* Ah = (t == 0) ? g_zh0 : (g_Zh + (size_t)(t-1)*BB*HH);
        const __half* Al = (t == 0) ? g_zh0 : (g_Zl + (size_t)(t-1)*BB*HH);

        auto waitgrp = [&](int c){
            if (t == 0) return;
            const unsigned* fp = &g_cnt[(size_t)(t-1)*16 + bq*4 + half*2 + c];
            if (lane == 0){
                unsigned v;
                do { asm volatile("ld.acquire.gpu.u32 %0, [%1];" : "=r"(v) : "l"(fp) : "memory");
                     if (v != 8u) __nanosleep(16);
                } while (v != 8u);
            }
            __syncwarp();
        };
        auto loadA = [&](int c){
            uint32_t ab = sb + A_OFF + (uint32_t)(half*2 + c)*ABUF;
            int kbase = half*256 + c*128;
            #pragma unroll
            for (int q = 0; q < 8; q++){
                int idx = t128 + 128*q;
                int row = idx >> 4, kg = idx & 15;
                uint32_t dst = ab + (uint32_t)(row*256 + ((kg ^ (row & 7)) << 4));
                size_t src = (size_t)(b0+row)*HH + kbase + kg*8;
                cpa16(dst,          Ah + src);
                cpa16(dst + 16384u, Al + src);
            }
            asm volatile("cp.async.commit_group;");
        };
        waitgrp(0); loadA(0);
        waitgrp(1); loadA(1);

        float acc[6][4];
        #pragma unroll
        for (int p = 0; p < 6; p++)
            #pragma unroll
            for (int e = 0; e < 4; e++) acc[p][e] = 0.0f;

        #pragma unroll 1
        for (int c = 0; c < 2; c++){
            if (c == 0) asm volatile("cp.async.wait_group 1;");
            else        asm volatile("cp.async.wait_group 0;");
            if (half == 0) asm volatile("bar.sync 1, 128;" ::: "memory");
            else           asm volatile("bar.sync 2, 128;" ::: "memory");

            uint32_t abuf = sb + A_OFF + (uint32_t)(half*2 + c)*ABUF;
            int rowA = m0 + (lane & 15);
            uint32_t aRowBase = abuf + (uint32_t)(rowA*256);
            #pragma unroll
            for (int s = 0; s < 8; s++){
                uint32_t ah[4], al[4];
                int kgA = s*2 + (lane >> 4);
                uint32_t aoff = aRowBase + (uint32_t)((kgA ^ (lane & 7)) << 4);
                ldsm4(aoff, ah);
                ldsm4(aoff + 16384u, al);
                int kgB = half*32 + c*16 + s*2 + ((lane >> 3) & 1);
                #pragma unroll
                for (int p = 0; p < 3; p++){
                    int rowB = p*16 + (lane & 7) + ((lane >> 4) << 3);
                    uint32_t boff = (uint32_t)(rowB*1024 + ((kgB ^ (lane & 7)) << 4));
                    uint32_t bh[4];
                    ldsm4(sb + BH_OFF + boff, bh);
                    mma16816(acc[2*p],   ah, bh + 0);
                    mma16816(acc[2*p],   al, bh + 0);
                    mma16816(acc[2*p+1], ah, bh + 2);
                    mma16816(acc[2*p+1], al, bh + 2);
                }
            }
        }

        // symmetric cross-half exchange
        __syncthreads();
        float4* xbase = (float4*)(smem + A_OFF);
        {
            int eo2 = 2*(half^1);
            float4* w = xbase + (size_t)((half^1)*128 + wm*32 + lane)*3;
            w[0] = make_float4(acc[0][eo2], acc[0][eo2+1], acc[1][eo2], acc[1][eo2+1]);
            w[1] = make_float4(acc[2][eo2], acc[2][eo2+1], acc[3][eo2], acc[3][eo2+1]);
            w[2] = make_float4(acc[4][eo2], acc[4][eo2+1], acc[5][eo2], acc[5][eo2+1]);
        }
        __syncthreads();
        const int eo = 2*half;
        {
            float4* r = xbase + (size_t)(half*128 + wm*32 + lane)*3;
            float4 v0 = r[0], v1 = r[1], v2 = r[2];
            acc[0][eo] += v0.x; acc[0][eo+1] += v0.y; acc[1][eo] += v0.z; acc[1][eo+1] += v0.w;
            acc[2][eo] += v1.x; acc[2][eo+1] += v1.y; acc[3][eo] += v1.z; acc[3][eo+1] += v1.w;
            acc[4][eo] += v2.x; acc[4][eo+1] += v2.y; acc[5][eo] += v2.z; acc[5][eo+1] += v2.w;
        }

        // fused gate epilogue for my row
        {
            uint32_t hw[2], lw[2];
            #pragma unroll
            for (int g = 0; g < 2; g++){
                float hn2[2];
                #pragma unroll
                for (int e = 0; e < 2; e++){
                    int jl = 8*g + cp + e;
                    float pr = acc[0+g][eo+e] + sBias[jl];
                    float pz = acc[2+g][eo+e] + sBias[16+jl];
                    float pn = acc[4+g][eo+e] + sBias[32+jl];
                    const float* gr = (const float*)&gg[0][g];
                    const float* gz = (const float*)&gg[1][g];
                    const float* gn = (const float*)&gg[2][g];
                    float r  = sigf(gr[e] + pr);
                    float z  = sigf(gz[e] + pz);
                    float nn = tanhf(gn[e] + r * pn);
                    float hn = (1.0f - z) * nn + z * hp[g][e];
                    hp[g][e] = hn;
                    hn2[e] = hn;
                }
                __half a0 = __float2half_rn(hn2[0]);
                __half a1 = __float2half_rn(hn2[1]);
                __half c0 = __float2half_rn(hn2[0] - __half2float(a0));
                __half c1 = __float2half_rn(hn2[1] - __half2float(a1));
                __half2 hv = __halves2half2(a0, a1);
                __half2 lv = __halves2half2(c0, c1);
                hw[g] = *(uint32_t*)&hv;
                lw[g] = *(uint32_t*)&lv;
            }
            size_t o = ((size_t)t*BB + bmine)*HH + h0 + cp;
            *(uint32_t*)(g_Zh + o)     = hw[0];
            *(uint32_t*)(g_Zh + o + 8) = hw[1];
            *(uint32_t*)(g_Zl + o)     = lw[0];
            *(uint32_t*)(g_Zl + o + 8) = lw[1];
        }

        __syncthreads();
        if (tid == 0){
            asm volatile("red.release.gpu.global.add.u32 [%0], %1;"
                         :: "l"(&g_cnt[(size_t)t*16 + bq*4 + (hg >> 3)]), "r"(1u) : "memory");
        }
    }
}

// ---------------- Phase 3: V = bias + (Zh+Zl) . vw ----------------
__global__ __launch_bounds__(256) void value_kernel(const float* __restrict__ vw,
                                                    const float* __restrict__ bias,
                                                    float* __restrict__ out)
{
    int warp = (blockIdx.x * 256 + threadIdx.x) >> 5;
    int lane = threadIdx.x & 31;
    const __half* zh = g_Zh + (size_t)warp * HH;
    const __half* zl = g_Zl + (size_t)warp * HH;
    float s = 0.0f;
    #pragma unroll
    for (int i = 0; i < 4; i++){
        int idx = i*128 + lane*4;
        uint2 ah = *(const uint2*)(zh + idx);
        uint2 al = *(const uint2*)(zl + idx);
        float4 wv = *(const float4*)(&vw[idx]);
        __half2 h0 = *(__half2*)&ah.x;
        __half2 h1 = *(__half2*)&ah.y;
        __half2 l0 = *(__half2*)&al.x;
        __half2 l1 = *(__half2*)&al.y;
        s += (__half2float(h0.x) + __half2float(l0.x)) * wv.x;
        s += (__half2float(h0.y) + __half2float(l0.y)) * wv.y;
        s += (__half2float(h1.x) + __half2float(l1.x)) * wv.z;
        s += (__half2float(h1.y) + __half2float(l1.y)) * wv.w;
    }
    #pragma unroll
    for (int o = 16; o > 0; o >>= 1)
        s += __shfl_xor_sync(0xFFFFFFFFu, s, o);
    if (lane == 0) out[warp] = s + bias[0];
}

extern "C" void kernel_launch(void* const* d_in, const int* in_sizes, int n_in,
                              void* d_out, int out_size)
{
    const float* X    = (const float*)d_in[0];
    const float* Wih  = (const float*)d_in[1];
    const float* Whh  = (const float*)d_in[2];
    const float* bih  = (const float*)d_in[3];
    const float* bhh  = (const float*)d_in[4];
    const float* vw   = (const float*)d_in[5];
    const float* bias = (const float*)d_in[6];
    float* out = (float*)d_out;

    static int smem_set = 0;
    if (!smem_set){
        cudaFuncSetAttribute(step_tc, cudaFuncAttributeMaxDynamicSharedMemorySize, SMEM_TC);
        cudaFuncSetAttribute(gi_hmma, cudaFuncAttributeMaxDynamicSharedMemorySize, SMEM_GI);
        smem_set = 1;
    }

    cvt_kernel<<<8192 + 96, 256>>>(X, Wih);

    gi_hmma<<<dim3(RT/128, G3/64), 256, SMEM_GI>>>(bih);

    step_tc<<<dim3(4, 32), 256, SMEM_TC>>>(Whh, bhh);

    value_kernel<<<RT/8, 256>>>(vw, bias, out);
}

// round 16
// speedup vs baseline: 3.3549x; 1.1052x over previous
#include <cuda_runtime.h>
#include <cuda_fp16.h>
#include <cstdint>

#define TT 512
#define BB 256
#define II 64
#define HH 512
#define G3 1536
#define RT (TT*BB)

typedef unsigned long long u64;

// ---------------- scratch ----------------
__device__ float g_gi2[(size_t)TT * 32 * 256 * 48];   // [t][hg][b][jl+16*gate]
__device__ __half g_Xh[(size_t)RT * II];              // X fp16 hi
__device__ __half g_Xl[(size_t)RT * II];              // X fp16 lo
__device__ __half g_Wh[(size_t)G3 * II];              // Wih fp16 hi
__device__ __half g_Wl[(size_t)G3 * II];              // Wih fp16 lo
__device__ __half g_Z [(size_t)RT * HH];              // h fp16 [t][b][k]
__device__ __half g_zh0[BB * HH];                     // zeros
__device__ unsigned g_cnt[TT * 16];                   // [t][bq][kgroup]
struct __align__(128) Bar { unsigned cnt; unsigned gen; unsigned pad[30]; };
__device__ Bar g_bar0;

// ---------------- step smem layout ----------------
#define SM_BIAS 0
#define A_OFF   1024
#define ABUF    16384                    // per chunk buffer (hi only)
#define BH_OFF  (A_OFF + 4*ABUF)         // 66560
#define SMEM_TC (BH_OFF + 49152)         // 115712

// ---------------- gi smem layout ----------------
#define GXH 0
#define GXL 16384
#define GWH 32768
#define GWL 40960
#define SMEM_GI 49152

static __device__ __forceinline__ uint32_t s2u(const void* p){
    return (uint32_t)__cvta_generic_to_shared(p);
}
static __device__ __forceinline__ float sigf(float x){
    return __fdividef(1.0f, 1.0f + __expf(-x));
}
static __device__ __forceinline__ void cpa16(uint32_t dst, const void* src){
    asm volatile("cp.async.ca.shared.global [%0], [%1], 16;" :: "r"(dst), "l"(src));
}
static __device__ __forceinline__ void ldsm4(uint32_t a, uint32_t (&r)[4]){
    asm volatile("ldmatrix.sync.aligned.m8n8.x4.shared.b16 {%0,%1,%2,%3}, [%4];"
        : "=r"(r[0]), "=r"(r[1]), "=r"(r[2]), "=r"(r[3]) : "r"(a));
}
static __device__ __forceinline__ void mma16816(float (&d)[4], const uint32_t (&a)[4],
                                                const uint32_t* b){
    asm volatile("mma.sync.aligned.m16n8k16.row.col.f32.f16.f16.f32 "
        "{%0,%1,%2,%3}, {%4,%5,%6,%7}, {%8,%9}, {%0,%1,%2,%3};"
        : "+f"(d[0]), "+f"(d[1]), "+f"(d[2]), "+f"(d[3])
        : "r"(a[0]), "r"(a[1]), "r"(a[2]), "r"(a[3]), "r"(b[0]), "r"(b[1]));
}

// ---------------- Phase 0: fp16 hi/lo conversion of X and Wih ----------------
__global__ __launch_bounds__(256) void cvt_kernel(const float* __restrict__ X,
                                                  const float* __restrict__ Wih)
{
    int bx = blockIdx.x;
    const float* src; __half *dh, *dl; size_t i;
    if (bx < 8192){
        i = ((size_t)bx*256 + threadIdx.x)*4;
        src = X; dh = g_Xh; dl = g_Xl;
    } else {
        i = ((size_t)(bx-8192)*256 + threadIdx.x)*4;
        if (i >= (size_t)G3*II) return;
        src = Wih; dh = g_Wh; dl = g_Wl;
    }
    float4 v = *(const float4*)(src + i);
    __half h0 = __float2half_rn(v.x), h1 = __float2half_rn(v.y);
    __half h2 = __float2half_rn(v.z), h3 = __float2half_rn(v.w);
    __half l0 = __float2half_rn(v.x - __half2float(h0));
    __half l1 = __float2half_rn(v.y - __half2float(h1));
    __half l2 = __float2half_rn(v.z - __half2float(h2));
    __half l3 = __float2half_rn(v.w - __half2float(h3));
    __half2 hA = __halves2half2(h0, h1), hB = __halves2half2(h2, h3);
    __half2 lA = __halves2half2(l0, l1), lB = __halves2half2(l2, l3);
    *(uint2*)(dh + i) = make_uint2(*(uint32_t*)&hA, *(uint32_t*)&hB);
    *(uint2*)(dl + i) = make_uint2(*(uint32_t*)&lA, *(uint32_t*)&lB);
}

// ---------------- Phase 1: gi via HMMA (fp16 3-term) ----------------
#define CST 68
__global__ __launch_bounds__(256) void gi_hmma(const float* __restrict__ bih)
{
    extern __shared__ __align__(1024) char smem[];
    const uint32_t sb = s2u(smem);
    const int tid = threadIdx.x;
    const int wid = tid >> 5, lane = tid & 31;
    const int wm2 = wid >> 1, wn = wid & 1;
    const int r0 = blockIdx.x * 128;
    const int c0 = blockIdx.y * 64;

    #pragma unroll
    for (int q = 0; q < 4; q++){
        int idx = tid + 256*q;            // 0..1023
        int row = idx >> 3, kg = idx & 7;
        uint32_t off = (uint32_t)(row*128 + ((kg ^ (row & 7)) << 4));
        size_t src = (size_t)(r0+row)*II + kg*8;
        cpa16(sb + GXH + off, g_Xh + src);
        cpa16(sb + GXL + off, g_Xl + src);
    }
    #pragma unroll
    for (int q = 0; q < 2; q++){
        int idx = tid + 256*q;            // 0..511
        int n = idx >> 3, kg = idx & 7;
        uint32_t off = (uint32_t)(n*128 + ((kg ^ (n & 7)) << 4));
        size_t src = (size_t)(c0+n)*II + kg*8;
        cpa16(sb + GWH + off, g_Wh + src);
        cpa16(sb + GWL + off, g_Wl + src);
    }
    asm volatile("cp.async.commit_group;");
    asm volatile("cp.async.wait_group 0;");
    __syncthreads();

    float acc[2][4][4];
    #pragma unroll
    for (int f = 0; f < 2; f++)
        #pragma unroll
        for (int n8 = 0; n8 < 4; n8++)
            #pragma unroll
            for (int e = 0; e < 4; e++) acc[f][n8][e] = 0.0f;

    #pragma unroll
    for (int ks = 0; ks < 4; ks++){
        uint32_t ah[2][4], al[2][4];
        #pragma unroll
        for (int f = 0; f < 2; f++){
            int rowA = wm2*32 + f*16 + (lane & 15);
            int kgA  = ks*2 + (lane >> 4);
            uint32_t off = (uint32_t)(rowA*128 + ((kgA ^ (rowA & 7)) << 4));
            ldsm4(sb + GXH + off, ah[f]);
            ldsm4(sb + GXL + off, al[f]);
        }
        #pragma unroll
        for (int nf = 0; nf < 2; nf++){
            int rowB = wn*32 + nf*16 + (lane & 7) + ((lane >> 4) << 3);
            int kgB  = ks*2 + ((lane >> 3) & 1);
            uint32_t boff = (uint32_t)(rowB*128 + ((kgB ^ (rowB & 7)) << 4));
            uint32_t bh[4], bl[4];
            ldsm4(sb + GWH + boff, bh);
            ldsm4(sb + GWL + boff, bl);
            #pragma unroll
            for (int f = 0; f < 2; f++){
                mma16816(acc[f][nf*2],   ah[f], bh + 0);
                mma16816(acc[f][nf*2],   al[f], bh + 0);
                mma16816(acc[f][nf*2],   ah[f], bl + 0);
                mma16816(acc[f][nf*2+1], ah[f], bh + 2);
                mma16816(acc[f][nf*2+1], al[f], bh + 2);
                mma16816(acc[f][nf*2+1], ah[f], bl + 2);
            }
        }
    }
    __syncthreads();

    float* Cs = (float*)smem;
    #pragma unroll
    for (int f = 0; f < 2; f++)
        #pragma unroll
        for (int n8 = 0; n8 < 4; n8++){
            int R = wm2*32 + f*16 + (lane >> 2);
            int C = wn*32 + n8*8 + (lane & 3)*2;
            Cs[R*CST + C]       = acc[f][n8][0];
            Cs[R*CST + C + 1]   = acc[f][n8][1];
            Cs[(R+8)*CST + C]   = acc[f][n8][2];
            Cs[(R+8)*CST + C+1] = acc[f][n8][3];
        }
    __syncthreads();

    const int gate = c0 >> 9;
    const int tt   = r0 >> 8;
    const int b0r  = r0 & 255;
    const int hg0  = (c0 & 511) >> 4;
    float4* go = (float4*)g_gi2;
    #pragma unroll
    for (int q = 0; q < 8; q++){
        int f   = tid + 256*q;            // 0..2047
        int row = f >> 4;
        int cc4 = f & 15;
        float4 v  = *(const float4*)&Cs[row*CST + cc4*4];
        float4 bv = *(const float4*)&bih[c0 + cc4*4];
        v.x += bv.x; v.y += bv.y; v.z += bv.z; v.w += bv.w;
        size_t a4 = ((size_t)(tt*32 + hg0 + (cc4 >> 2))*256 + b0r + row)*12
                  + (cc4 & 3) + 4*gate;
        go[a4] = v;
    }
}

// ---------------- Phase 2: persistent HMMA GRU, single-fp16 h, K-split ----------------
__global__ __launch_bounds__(256, 1) void step_tc(const float* __restrict__ Whh,
                                                  const float* __restrict__ bhh)
{
    extern __shared__ __align__(1024) char smem[];
    const uint32_t sb = s2u(smem);
    const int tid  = threadIdx.x;
    const int wid  = tid >> 5, lane = tid & 31;
    const int half = wid >> 2;            // 0: k[0,256), 1: k[256,512)
    const int wm   = wid & 3;
    const int t128 = tid & 127;
    const int bq   = blockIdx.x;
    const int hg   = blockIdx.y;
    const int b0   = bq * 64;
    const int h0   = hg * 16;
    const int m0   = wm * 16;
    const int r0   = lane >> 2;
    const int cp   = (lane & 3) * 2;
    const int bmine = b0 + m0 + r0 + 8*half;

    float* sBias = (float*)(smem + SM_BIAS);
    if (tid < 48) sBias[tid] = bhh[(tid >> 4)*HH + h0 + (tid & 15)];

    // resident W fp16, rows [n][k], 16B-group XOR swizzle
    for (int it = 0; it < 48; it++){
        int idx = tid + 256*it;
        int n   = idx >> 8;
        int k2  = idx & 255;
        int grow = (n >> 4)*HH + h0 + (n & 15);
        float2 w = *(const float2*)&Whh[(size_t)grow*HH + k2*2];
        __half2 hv = __halves2half2(__float2half_rn(w.x), __float2half_rn(w.y));
        int k = k2*2, kg = k >> 3;
        uint32_t off = (uint32_t)(n*1024 + ((kg ^ (n & 7)) << 4) + (k & 7)*2);
        *(uint32_t*)(smem + BH_OFF + off) = *(uint32_t*)&hv;
    }

    for (int i = tid; i < TT*16; i += 256) g_cnt[i] = 0;
    __threadfence();
    __syncthreads();
    if (tid == 0){
        unsigned gen;
        asm volatile("ld.acquire.gpu.u32 %0, [%1];" : "=r"(gen) : "l"(&g_bar0.gen) : "memory");
        unsigned arr = atomicAdd(&g_bar0.cnt, 1);
        if (arr == 127){
            atomicExch(&g_bar0.cnt, 0);
            __threadfence();
            atomicAdd(&g_bar0.gen, 1);
        } else {
            unsigned g;
            do { __nanosleep(32);
                 asm volatile("ld.acquire.gpu.u32 %0, [%1];" : "=r"(g) : "l"(&g_bar0.gen) : "memory");
            } while (g == gen);
        }
    }
    __syncthreads();

    float hp[2][2];
    #pragma unroll
    for (int g = 0; g < 2; g++)
        #pragma unroll
        for (int e = 0; e < 2; e++) hp[g][e] = 0.0f;

    for (int t = 0; t < TT; t++){
        float2 gg[3][2];
        {
            const float* gp = g_gi2 + ((((size_t)t*32 + hg)*256 + bmine)*48);
            #pragma unroll
            for (int gate = 0; gate < 3; gate++)
                #pragma unroll
                for (int g = 0; g < 2; g++)
                    gg[gate][g] = __ldg((const float2*)(gp + gate*16 + 8*g + cp));
        }

        const __half* Ah = (t == 0) ? g_zh0 : (g_Z + (size_t)(t-1)*BB*HH);

        auto waitgrp = [&](int c){
            if (t == 0) return;
            const unsigned* fp = &g_cnt[(size_t)(t-1)*16 + bq*4 + half*2 + c];
            if (lane == 0){
                unsigned v;
                do { asm volatile("ld.acquire.gpu.u32 %0, [%1];" : "=r"(v) : "l"(fp) : "memory");
                     if (v != 8u) __nanosleep(16);
                } while (v != 8u);
            }
            __syncwarp();
        };
        auto loadA = [&](int c){
            uint32_t ab = sb + A_OFF + (uint32_t)(half*2 + c)*ABUF;
            int kbase = half*256 + c*128;
            #pragma unroll
            for (int q = 0; q < 8; q++){
                int idx = t128 + 128*q;
                int row = idx >> 4, kg = idx & 15;
                uint32_t dst = ab + (uint32_t)(row*256 + ((kg ^ (row & 7)) << 4));
                cpa16(dst, Ah + (size_t)(b0+row)*HH + kbase + kg*8);
            }
            asm volatile("cp.async.commit_group;");
        };
        waitgrp(0); loadA(0);
        waitgrp(1); loadA(1);

        float acc[6][4];
        #pragma unroll
        for (int p = 0; p < 6; p++)
            #pragma unroll
            for (int e = 0; e < 4; e++) acc[p][e] = 0.0f;

        #pragma unroll 1
        for (int c = 0; c < 2; c++){
            if (c == 0) asm volatile("cp.async.wait_group 1;");
            else        asm volatile("cp.async.wait_group 0;");
            if (half == 0) asm volatile("bar.sync 1, 128;" ::: "memory");
            else           asm volatile("bar.sync 2, 128;" ::: "memory");

            uint32_t abuf = sb + A_OFF + (uint32_t)(half*2 + c)*ABUF;
            int rowA = m0 + (lane & 15);
            uint32_t aRowBase = abuf + (uint32_t)(rowA*256);
            #pragma unroll
            for (int s = 0; s < 8; s++){
                uint32_t ah[4];
                int kgA = s*2 + (lane >> 4);
                ldsm4(aRowBase + (uint32_t)((kgA ^ (lane & 7)) << 4), ah);
                int kgB = half*32 + c*16 + s*2 + ((lane >> 3) & 1);
                #pragma unroll
                for (int p = 0; p < 3; p++){
                    int rowB = p*16 + (lane & 7) + ((lane >> 4) << 3);
                    uint32_t boff = (uint32_t)(rowB*1024 + ((kgB ^ (lane & 7)) << 4));
                    uint32_t bh[4];
                    ldsm4(sb + BH_OFF + boff, bh);
                    mma16816(acc[2*p],   ah, bh + 0);
                    mma16816(acc[2*p+1], ah, bh + 2);
                }
            }
        }

        // symmetric cross-half exchange
        __syncthreads();
        float4* xbase = (float4*)(smem + A_OFF);
        {
            int eo2 = 2*(half^1);
            float4* w = xbase + (size_t)((half^1)*128 + wm*32 + lane)*3;
            w[0] = make_float4(acc[0][eo2], acc[0][eo2+1], acc[1][eo2], acc[1][eo2+1]);
            w[1] = make_float4(acc[2][eo2], acc[2][eo2+1], acc[3][eo2], acc[3][eo2+1]);
            w[2] = make_float4(acc[4][eo2], acc[4][eo2+1], acc[5][eo2], acc[5][eo2+1]);
        }
        __syncthreads();
        const int eo = 2*half;
        {
            float4* r = xbase + (size_t)(half*128 + wm*32 + lane)*3;
            float4 v0 = r[0], v1 = r[1], v2 = r[2];
            acc[0][eo] += v0.x; acc[0][eo+1] += v0.y; acc[1][eo] += v0.z; acc[1][eo+1] += v0.w;
            acc[2][eo] += v1.x; acc[2][eo+1] += v1.y; acc[3][eo] += v1.z; acc[3][eo+1] += v1.w;
            acc[4][eo] += v2.x; acc[4][eo+1] += v2.y; acc[5][eo] += v2.z; acc[5][eo+1] += v2.w;
        }

        // fused gate epilogue for my row
        {
            uint32_t hw[2];
            #pragma unroll
            for (int g = 0; g < 2; g++){
                float hn2[2];
                #pragma unroll
                for (int e = 0; e < 2; e++){
                    int jl = 8*g + cp + e;
                    float pr = acc[0+g][eo+e] + sBias[jl];
                    float pz = acc[2+g][eo+e] + sBias[16+jl];
                    float pn = acc[4+g][eo+e] + sBias[32+jl];
                    const float* gr = (const float*)&gg[0][g];
                    const float* gz = (const float*)&gg[1][g];
                    const float* gn = (const float*)&gg[2][g];
                    float r  = sigf(gr[e] + pr);
                    float z  = sigf(gz[e] + pz);
                    float nn = tanhf(gn[e] + r * pn);
                    float hn = (1.0f - z) * nn + z * hp[g][e];
                    hp[g][e] = hn;
                    hn2[e] = hn;
                }
                __half2 hv = __halves2half2(__float2half_rn(hn2[0]), __float2half_rn(hn2[1]));
                hw[g] = *(uint32_t*)&hv;
            }
            size_t o = ((size_t)t*BB + bmine)*HH + h0 + cp;
            *(uint32_t*)(g_Z + o)     = hw[0];
            *(uint32_t*)(g_Z + o + 8) = hw[1];
        }

        __syncthreads();
        if (tid == 0){
            asm volatile("red.release.gpu.global.add.u32 [%0], %1;"
                         :: "l"(&g_cnt[(size_t)t*16 + bq*4 + (hg >> 3)]), "r"(1u) : "memory");
        }
    }
}

// ---------------- Phase 3: V = bias + Z . vw ----------------
__global__ __launch_bounds__(256) void value_kernel(const float* __restrict__ vw,
                                                    const float* __restrict__ bias,
                                                    float* __restrict__ out)
{
    int warp = (blockIdx.x * 256 + threadIdx.x) >> 5;
    int lane = threadIdx.x & 31;
    const __half* z = g_Z + (size_t)warp * HH;
    float s = 0.0f;
    #pragma unroll
    for (int i = 0; i < 4; i++){
        int idx = i*128 + lane*4;
        uint2 ah = *(const uint2*)(z + idx);
        float4 wv = *(const float4*)(&vw[idx]);
        __half2 h0 = *(__half2*)&ah.x;
        __half2 h1 = *(__half2*)&ah.y;
        s += __half2float(h0.x) * wv.x;
        s += __half2float(h0.y) * wv.y;
        s += __half2float(h1.x) * wv.z;
        s += __half2float(h1.y) * wv.w;
    }
    #pragma unroll
    for (int o = 16; o > 0; o >>= 1)
        s += __shfl_xor_sync(0xFFFFFFFFu, s, o);
    if (lane == 0) out[warp] = s + bias[0];
}

extern "C" void kernel_launch(void* const* d_in, const int* in_sizes, int n_in,
                              void* d_out, int out_size)
{
    const float* X    = (const float*)d_in[0];
    const float* Wih  = (const float*)d_in[1];
    const float* Whh  = (const float*)d_in[2];
    const float* bih  = (const float*)d_in[3];
    const float* bhh  = (const float*)d_in[4];
    const float* vw   = (const float*)d_in[5];
    const float* bias = (const float*)d_in[6];
    float* out = (float*)d_out;

    static int smem_set = 0;
    if (!smem_set){
        cudaFuncSetAttribute(step_tc, cudaFuncAttributeMaxDynamicSharedMemorySize, SMEM_TC);
        cudaFuncSetAttribute(gi_hmma, cudaFuncAttributeMaxDynamicSharedMemorySize, SMEM_GI);
        smem_set = 1;
    }

    cvt_kernel<<<8192 + 96, 256>>>(X, Wih);

    gi_hmma<<<dim3(RT/128, G3/64), 256, SMEM_GI>>>(bih);

    step_tc<<<dim3(4, 32), 256, SMEM_TC>>>(Whh, bhh);

    value_kernel<<<RT/8, 256>>>(vw, bias, out);
}